// round 1
// baseline (speedup 1.0000x reference)
#include <cuda_runtime.h>
#include <cuda_bf16.h>
#include <math.h>

// Problem constants
#define Bsz   2
#define Sseq  2048
#define Dmod  2048
#define Hh    16
#define DKk   128
#define Ll    64
#define Mrows (Bsz * Sseq)   // 4096

// ---------------------------------------------------------------------------
// Device scratch (no allocation allowed in kernel_launch)
// ---------------------------------------------------------------------------
__device__ float g_Q [(size_t)Mrows * Dmod];
__device__ float g_K [(size_t)Mrows * Dmod];
__device__ float g_V [(size_t)Mrows * Dmod];
__device__ float g_O [(size_t)Mrows * Dmod];
__device__ float g_Wk[(size_t)Dmod * Dmod];
__device__ float g_Wv[(size_t)Dmod * Dmod];
__device__ float g_bk[Dmod];
__device__ float g_bv[Dmod];

// ---------------------------------------------------------------------------
// Weight fold: Weff[d, h*128+c] = sum_l Wl[d, h*64+l] * Wr[l, c]
// ---------------------------------------------------------------------------
__global__ __launch_bounds__(128) void fold_w_kernel(
    const float* __restrict__ Wl, const float* __restrict__ Wr,
    float* __restrict__ Weff)
{
    const int d = blockIdx.x;
    const int h = blockIdx.y;
    const int c = threadIdx.x;  // 0..127
    __shared__ float sl[Ll];
    if (c < Ll) sl[c] = Wl[(size_t)d * (Hh * Ll) + h * Ll + c];
    __syncthreads();
    float acc = 0.f;
    #pragma unroll 16
    for (int l = 0; l < Ll; l++)
        acc += sl[l] * Wr[l * DKk + c];
    Weff[(size_t)d * Dmod + h * DKk + c] = acc;
}

__global__ __launch_bounds__(128) void fold_b_kernel(
    const float* __restrict__ bl, const float* __restrict__ Wr,
    const float* __restrict__ br, float* __restrict__ beff)
{
    const int h = blockIdx.x;
    const int c = threadIdx.x;
    float acc = br[c];
    #pragma unroll 16
    for (int l = 0; l < Ll; l++)
        acc += bl[h * Ll + l] * Wr[l * DKk + c];
    beff[h * DKk + c] = acc;
}

// ---------------------------------------------------------------------------
// FP32 tiled GEMM:  C[M,N] = A[M,K] @ W[K,N] + bias[N]
// BM=128, BN=64, BK=16, 256 threads, 8x4 micro-tile per thread.
// Interleaved (stride-16) row/col mapping -> conflict-free compute reads.
// ---------------------------------------------------------------------------
__global__ __launch_bounds__(256) void gemm_bias_kernel(
    const float* __restrict__ A, const float* __restrict__ W,
    const float* __restrict__ bias, float* __restrict__ C,
    int M, int N, int K)
{
    __shared__ float As[16 * 129];  // As[kk][row], padded
    __shared__ float Bs[16 * 64];   // Bs[kk][col]

    const int t  = threadIdx.x;
    const int tx = t & 15;
    const int ty = t >> 4;
    const int m0 = blockIdx.y * 128;
    const int n0 = blockIdx.x * 64;

    float acc[8][4];
    #pragma unroll
    for (int ii = 0; ii < 8; ii++)
        #pragma unroll
        for (int jj = 0; jj < 4; jj++)
            acc[ii][jj] = 0.f;

    for (int k0 = 0; k0 < K; k0 += 16) {
        // Load A tile [128][16] transposed into As[kk][row]
        #pragma unroll
        for (int i = 0; i < 2; i++) {
            int idx  = t + i * 256;      // 0..511 float4 units: [128 rows][4 f4]
            int row  = idx >> 2;
            int kkb  = idx & 3;
            float4 a4 = *(const float4*)(A + (size_t)(m0 + row) * K + k0 + kkb * 4);
            int kk = kkb * 4;
            As[(kk + 0) * 129 + row] = a4.x;
            As[(kk + 1) * 129 + row] = a4.y;
            As[(kk + 2) * 129 + row] = a4.z;
            As[(kk + 3) * 129 + row] = a4.w;
        }
        // Load B tile [16][64]
        {
            int kk   = t >> 4;
            int colb = t & 15;
            float4 b4 = *(const float4*)(W + (size_t)(k0 + kk) * N + n0 + colb * 4);
            *(float4*)&Bs[kk * 64 + colb * 4] = b4;
        }
        __syncthreads();

        #pragma unroll
        for (int kk = 0; kk < 16; kk++) {
            float a[8], bb[4];
            #pragma unroll
            for (int ii = 0; ii < 8; ii++) a[ii] = As[kk * 129 + ty + 16 * ii];
            #pragma unroll
            for (int jj = 0; jj < 4; jj++) bb[jj] = Bs[kk * 64 + tx + 16 * jj];
            #pragma unroll
            for (int ii = 0; ii < 8; ii++)
                #pragma unroll
                for (int jj = 0; jj < 4; jj++)
                    acc[ii][jj] = fmaf(a[ii], bb[jj], acc[ii][jj]);
        }
        __syncthreads();
    }

    #pragma unroll
    for (int ii = 0; ii < 8; ii++) {
        int row = m0 + ty + 16 * ii;
        #pragma unroll
        for (int jj = 0; jj < 4; jj++) {
            int col = n0 + tx + 16 * jj;
            C[(size_t)row * N + col] = acc[ii][jj] + bias[col];
        }
    }
}

// ---------------------------------------------------------------------------
// Fused causal flash attention (fp32, online softmax).
// Q/K/V/O layout: [b, s, h*128 + d]. One block = 64 query rows of one (b,h).
// smem: Qt[128][65], Kt[128][65] (transposed, conflict-free QK^T),
//       V[64][128], P[64][65].
// ---------------------------------------------------------------------------
#define FA_SMEM_FLOATS (128 * 65 + 128 * 65 + 64 * 128 + 64 * 65)

__global__ __launch_bounds__(256) void fa_kernel(
    const float* __restrict__ Q, const float* __restrict__ K,
    const float* __restrict__ V, float* __restrict__ O)
{
    extern __shared__ float sm[];
    float* sQt = sm;                   // [128][65]
    float* sKt = sQt + 128 * 65;       // [128][65]
    float* sV  = sKt + 128 * 65;       // [64][128]
    float* sP  = sV + 64 * 128;        // [64][65]
    float4* sV4 = (float4*)sV;

    const int qb = blockIdx.x;
    const int h  = blockIdx.y;
    const int b  = blockIdx.z;
    const int t  = threadIdx.x;
    const int tx = t & 15;
    const int ty = t >> 4;
    const int q0 = qb * 64;

    const size_t bh_off = (size_t)b * Sseq * Dmod + (size_t)h * DKk;
    const float* Qb = Q + bh_off + (size_t)q0 * Dmod;

    // Load Q tile [64][128] transposed into sQt[d][row]
    #pragma unroll
    for (int i = 0; i < 8; i++) {
        int idx  = t + i * 256;    // 2048 float4 units: [64 rows][32 f4]
        int row  = idx >> 5;
        int colb = idx & 31;
        float4 v4 = *(const float4*)(Qb + (size_t)row * Dmod + colb * 4);
        int d = colb * 4;
        sQt[(d + 0) * 65 + row] = v4.x;
        sQt[(d + 1) * 65 + row] = v4.y;
        sQt[(d + 2) * 65 + row] = v4.z;
        sQt[(d + 3) * 65 + row] = v4.w;
    }

    float m_i[4], l_i[4];
    float o_acc[4][8];
    #pragma unroll
    for (int ii = 0; ii < 4; ii++) {
        m_i[ii] = -1e30f;
        l_i[ii] = 0.f;
        #pragma unroll
        for (int jj = 0; jj < 8; jj++) o_acc[ii][jj] = 0.f;
    }
    __syncthreads();

    const float scale = 0.088388347648318447f;  // 1/sqrt(128)

    for (int kb = 0; kb <= qb; kb++) {
        const int kv0 = kb * 64;
        const float* Kb = K + bh_off + (size_t)kv0 * Dmod;
        const float* Vb = V + bh_off + (size_t)kv0 * Dmod;

        // Load K tile transposed, V tile row-major
        #pragma unroll
        for (int i = 0; i < 8; i++) {
            int idx  = t + i * 256;
            int row  = idx >> 5;
            int colb = idx & 31;
            float4 v4 = *(const float4*)(Kb + (size_t)row * Dmod + colb * 4);
            int d = colb * 4;
            sKt[(d + 0) * 65 + row] = v4.x;
            sKt[(d + 1) * 65 + row] = v4.y;
            sKt[(d + 2) * 65 + row] = v4.z;
            sKt[(d + 3) * 65 + row] = v4.w;
        }
        #pragma unroll
        for (int i = 0; i < 8; i++) {
            int idx  = t + i * 256;
            int row  = idx >> 5;
            int colb = idx & 31;
            sV4[row * 32 + colb] =
                *(const float4*)(Vb + (size_t)row * Dmod + colb * 4);
        }
        __syncthreads();

        // QK^T: 4x4 scores per thread, rows = ty+16*ii, cols = tx+16*jj
        float acc[4][4];
        #pragma unroll
        for (int ii = 0; ii < 4; ii++)
            #pragma unroll
            for (int jj = 0; jj < 4; jj++) acc[ii][jj] = 0.f;

        #pragma unroll 4
        for (int d = 0; d < 128; d++) {
            float a0 = sQt[d * 65 + ty];
            float a1 = sQt[d * 65 + ty + 16];
            float a2 = sQt[d * 65 + ty + 32];
            float a3 = sQt[d * 65 + ty + 48];
            float b0 = sKt[d * 65 + tx];
            float b1 = sKt[d * 65 + tx + 16];
            float b2 = sKt[d * 65 + tx + 32];
            float b3 = sKt[d * 65 + tx + 48];
            acc[0][0] = fmaf(a0, b0, acc[0][0]);
            acc[0][1] = fmaf(a0, b1, acc[0][1]);
            acc[0][2] = fmaf(a0, b2, acc[0][2]);
            acc[0][3] = fmaf(a0, b3, acc[0][3]);
            acc[1][0] = fmaf(a1, b0, acc[1][0]);
            acc[1][1] = fmaf(a1, b1, acc[1][1]);
            acc[1][2] = fmaf(a1, b2, acc[1][2]);
            acc[1][3] = fmaf(a1, b3, acc[1][3]);
            acc[2][0] = fmaf(a2, b0, acc[2][0]);
            acc[2][1] = fmaf(a2, b1, acc[2][1]);
            acc[2][2] = fmaf(a2, b2, acc[2][2]);
            acc[2][3] = fmaf(a2, b3, acc[2][3]);
            acc[3][0] = fmaf(a3, b0, acc[3][0]);
            acc[3][1] = fmaf(a3, b1, acc[3][1]);
            acc[3][2] = fmaf(a3, b2, acc[3][2]);
            acc[3][3] = fmaf(a3, b3, acc[3][3]);
        }

        // Online softmax update per owned row (16 threads per row, shfl width 16)
        #pragma unroll
        for (int ii = 0; ii < 4; ii++) {
            const int qrow = q0 + ty + 16 * ii;
            float s[4];
            float rmax = -1e30f;
            #pragma unroll
            for (int jj = 0; jj < 4; jj++) {
                int kcol = kv0 + tx + 16 * jj;
                float v = acc[ii][jj] * scale;
                if (kcol > qrow) v = -1e30f;
                s[jj] = v;
                rmax = fmaxf(rmax, v);
            }
            rmax = fmaxf(rmax, __shfl_xor_sync(0xFFFFFFFFu, rmax, 8));
            rmax = fmaxf(rmax, __shfl_xor_sync(0xFFFFFFFFu, rmax, 4));
            rmax = fmaxf(rmax, __shfl_xor_sync(0xFFFFFFFFu, rmax, 2));
            rmax = fmaxf(rmax, __shfl_xor_sync(0xFFFFFFFFu, rmax, 1));

            float m_new = fmaxf(m_i[ii], rmax);
            float corr  = __expf(m_i[ii] - m_new);
            float psum  = 0.f;
            #pragma unroll
            for (int jj = 0; jj < 4; jj++) {
                float p = __expf(s[jj] - m_new);
                sP[(ty + 16 * ii) * 65 + tx + 16 * jj] = p;
                psum += p;
            }
            psum += __shfl_xor_sync(0xFFFFFFFFu, psum, 8);
            psum += __shfl_xor_sync(0xFFFFFFFFu, psum, 4);
            psum += __shfl_xor_sync(0xFFFFFFFFu, psum, 2);
            psum += __shfl_xor_sync(0xFFFFFFFFu, psum, 1);

            l_i[ii] = l_i[ii] * corr + psum;
            m_i[ii] = m_new;
            #pragma unroll
            for (int jj = 0; jj < 8; jj++) o_acc[ii][jj] *= corr;
        }
        __syncthreads();

        // PV: O[row][tx*8 + 0..7] += P[row][kk] * V[kk][col]
        #pragma unroll 4
        for (int kk = 0; kk < 64; kk++) {
            float4 v0 = sV4[kk * 32 + tx * 2];
            float4 v1 = sV4[kk * 32 + tx * 2 + 1];
            #pragma unroll
            for (int ii = 0; ii < 4; ii++) {
                float p = sP[(ty + 16 * ii) * 65 + kk];
                o_acc[ii][0] = fmaf(p, v0.x, o_acc[ii][0]);
                o_acc[ii][1] = fmaf(p, v0.y, o_acc[ii][1]);
                o_acc[ii][2] = fmaf(p, v0.z, o_acc[ii][2]);
                o_acc[ii][3] = fmaf(p, v0.w, o_acc[ii][3]);
                o_acc[ii][4] = fmaf(p, v1.x, o_acc[ii][4]);
                o_acc[ii][5] = fmaf(p, v1.y, o_acc[ii][5]);
                o_acc[ii][6] = fmaf(p, v1.z, o_acc[ii][6]);
                o_acc[ii][7] = fmaf(p, v1.w, o_acc[ii][7]);
            }
        }
        __syncthreads();
    }

    // Epilogue: normalize and store in [b, s, h*128+d] layout
    float* Ob = O + bh_off + (size_t)q0 * Dmod;
    #pragma unroll
    for (int ii = 0; ii < 4; ii++) {
        float inv = 1.0f / l_i[ii];
        int row = ty + 16 * ii;
        float4 r0 = make_float4(o_acc[ii][0] * inv, o_acc[ii][1] * inv,
                                o_acc[ii][2] * inv, o_acc[ii][3] * inv);
        float4 r1 = make_float4(o_acc[ii][4] * inv, o_acc[ii][5] * inv,
                                o_acc[ii][6] * inv, o_acc[ii][7] * inv);
        *(float4*)(Ob + (size_t)row * Dmod + tx * 8)     = r0;
        *(float4*)(Ob + (size_t)row * Dmod + tx * 8 + 4) = r1;
    }
}

// ---------------------------------------------------------------------------
// kernel_launch
// ---------------------------------------------------------------------------
extern "C" void kernel_launch(void* const* d_in, const int* in_sizes, int n_in,
                              void* d_out, int out_size)
{
    const float* queries = (const float*)d_in[0];
    const float* keys    = (const float*)d_in[1];
    const float* values  = (const float*)d_in[2];
    const float* Wq      = (const float*)d_in[3];
    const float* bq      = (const float*)d_in[4];
    const float* Wlk     = (const float*)d_in[5];
    const float* blk     = (const float*)d_in[6];
    const float* Wlv     = (const float*)d_in[7];
    const float* blv     = (const float*)d_in[8];
    const float* Wkr     = (const float*)d_in[9];
    const float* bkr     = (const float*)d_in[10];
    const float* Wvr     = (const float*)d_in[11];
    const float* bvr     = (const float*)d_in[12];
    const float* Wo      = (const float*)d_in[13];
    const float* bo      = (const float*)d_in[14];
    float* out = (float*)d_out;

    float *Q, *K, *V, *O, *Wk, *Wv, *bk, *bv;
    cudaGetSymbolAddress((void**)&Q,  g_Q);
    cudaGetSymbolAddress((void**)&K,  g_K);
    cudaGetSymbolAddress((void**)&V,  g_V);
    cudaGetSymbolAddress((void**)&O,  g_O);
    cudaGetSymbolAddress((void**)&Wk, g_Wk);
    cudaGetSymbolAddress((void**)&Wv, g_Wv);
    cudaGetSymbolAddress((void**)&bk, g_bk);
    cudaGetSymbolAddress((void**)&bv, g_bv);

    // Fold latent + reconstruction weights into single effective projections
    fold_w_kernel<<<dim3(Dmod, Hh), 128>>>(Wlk, Wkr, Wk);
    fold_w_kernel<<<dim3(Dmod, Hh), 128>>>(Wlv, Wvr, Wv);
    fold_b_kernel<<<Hh, 128>>>(blk, Wkr, bkr, bk);
    fold_b_kernel<<<Hh, 128>>>(blv, Wvr, bvr, bv);

    // Projections: Q/K/V in [b, s, h*128+d] layout
    dim3 gg(Dmod / 64, Mrows / 128);
    gemm_bias_kernel<<<gg, 256>>>(queries, Wq, bq, Q, Mrows, Dmod, Dmod);
    gemm_bias_kernel<<<gg, 256>>>(keys,    Wk, bk, K, Mrows, Dmod, Dmod);
    gemm_bias_kernel<<<gg, 256>>>(values,  Wv, bv, V, Mrows, Dmod, Dmod);

    // Fused causal attention
    size_t fa_smem = (size_t)FA_SMEM_FLOATS * sizeof(float);
    cudaFuncSetAttribute(fa_kernel, cudaFuncAttributeMaxDynamicSharedMemorySize,
                         (int)fa_smem);
    fa_kernel<<<dim3(Sseq / 64, Hh, Bsz), 256, fa_smem>>>(Q, K, V, O);

    // Output projection
    gemm_bias_kernel<<<gg, 256>>>(O, Wo, bo, out, Mrows, Dmod, Dmod);
}

// round 3
// speedup vs baseline: 2.0822x; 2.0822x over previous
#include <cuda_runtime.h>
#include <cuda_bf16.h>
#include <math.h>
#include <cstdint>

// Problem constants
#define Bsz   2
#define Sseq  2048
#define Dmod  2048
#define Hh    16
#define DKk   128
#define Ll    64
#define Mrows (Bsz * Sseq)   // 4096

// ---------------------------------------------------------------------------
// Device scratch
// ---------------------------------------------------------------------------
__device__ float g_Q  [(size_t)Mrows * Dmod];
__device__ float g_K  [(size_t)Mrows * Dmod];
__device__ float g_V  [(size_t)Mrows * Dmod];
__device__ float g_O  [(size_t)Mrows * Dmod];
__device__ float g_Wtmp[(size_t)Dmod * Dmod];
__device__ float g_WqT[(size_t)Dmod * Dmod];
__device__ float g_WkT[(size_t)Dmod * Dmod];
__device__ float g_WvT[(size_t)Dmod * Dmod];
__device__ float g_WoT[(size_t)Dmod * Dmod];
__device__ float g_bk[Dmod];
__device__ float g_bv[Dmod];

// ---------------------------------------------------------------------------
// Helpers
// ---------------------------------------------------------------------------
__device__ __forceinline__ uint32_t smem_u32(const void* p) {
    uint32_t a;
    asm("{ .reg .u64 t; cvta.to.shared.u64 t, %1; cvt.u32.u64 %0, t; }"
        : "=r"(a) : "l"(p));
    return a;
}

#define CP_ASYNC16(dst, src) \
    asm volatile("cp.async.cg.shared.global [%0], [%1], 16;" \
        :: "r"((uint32_t)(dst)), "l"(src) : "memory")
#define CP_COMMIT() asm volatile("cp.async.commit_group;" ::: "memory")
#define CP_WAIT(n)  asm volatile("cp.async.wait_group %0;" :: "n"(n) : "memory")

__device__ __forceinline__ uint32_t f2tf32(float x) {
    uint32_t r;
    asm("cvt.rna.tf32.f32 %0, %1;" : "=r"(r) : "f"(x));
    return r;
}

// D = A @ B^T fragment op, accumulate in place.
__device__ __forceinline__ void mma_tf32(float* c, const uint32_t* a, const uint32_t* b) {
    asm volatile(
        "mma.sync.aligned.m16n8k8.row.col.f32.tf32.tf32.f32 "
        "{%0,%1,%2,%3}, {%4,%5,%6,%7}, {%8,%9}, {%0,%1,%2,%3};"
        : "+f"(c[0]), "+f"(c[1]), "+f"(c[2]), "+f"(c[3])
        : "r"(a[0]), "r"(a[1]), "r"(a[2]), "r"(a[3]), "r"(b[0]), "r"(b[1]));
}

// ---------------------------------------------------------------------------
// Weight fold: Weff[d, h*128+c] = sum_l Wl[d, h*64+l] * Wr[l, c]
// ---------------------------------------------------------------------------
__global__ __launch_bounds__(128) void fold_w_kernel(
    const float* __restrict__ Wl, const float* __restrict__ Wr,
    float* __restrict__ Weff)
{
    const int d = blockIdx.x;
    const int h = blockIdx.y;
    const int c = threadIdx.x;
    __shared__ float sl[Ll];
    if (c < Ll) sl[c] = Wl[(size_t)d * (Hh * Ll) + h * Ll + c];
    __syncthreads();
    float acc = 0.f;
    #pragma unroll 16
    for (int l = 0; l < Ll; l++)
        acc += sl[l] * Wr[l * DKk + c];
    Weff[(size_t)d * Dmod + h * DKk + c] = acc;
}

__global__ __launch_bounds__(128) void fold_b_kernel(
    const float* __restrict__ bl, const float* __restrict__ Wr,
    const float* __restrict__ br, float* __restrict__ beff)
{
    const int h = blockIdx.x;
    const int c = threadIdx.x;
    float acc = br[c];
    #pragma unroll 16
    for (int l = 0; l < Ll; l++)
        acc += bl[h * Ll + l] * Wr[l * DKk + c];
    beff[h * DKk + c] = acc;
}

// ---------------------------------------------------------------------------
// 32x32 tiled transpose: out[N,K] = in[K,N]^T   (square 2048x2048)
// ---------------------------------------------------------------------------
__global__ __launch_bounds__(256) void transpose_kernel(
    const float* __restrict__ in, float* __restrict__ out)
{
    __shared__ float tile[32][33];
    const int bx = blockIdx.x * 32;
    const int by = blockIdx.y * 32;
    const int tx = threadIdx.x & 31;
    const int ty = threadIdx.x >> 5;
    #pragma unroll
    for (int i = 0; i < 32; i += 8)
        tile[ty + i][tx] = in[(size_t)(by + ty + i) * Dmod + bx + tx];
    __syncthreads();
    #pragma unroll
    for (int i = 0; i < 32; i += 8)
        out[(size_t)(bx + ty + i) * Dmod + by + tx] = tile[tx][ty + i];
}

// ---------------------------------------------------------------------------
// Tensor-core tf32 GEMM:  C[M,N] = A[M,K] @ WT[N,K]^T + bias[N]
// CTA tile 128x128, BK=32, 2-stage cp.async pipeline, 256 threads (8 warps).
// Warp tile 64x32 = 4x4 fragments of m16n8k8.
// Smem tiles [128 rows][32 k] with row stride 36 floats:
//   - cp.async dst 16B-aligned (36*4 = 144 B row stride)
//   - fragment LDS bank = (4*row + col) % 32 -> conflict-free
// ---------------------------------------------------------------------------
#define G_BK 32
#define G_NK (Dmod / G_BK)       // 64
#define G_STRIDE 36              // floats per smem row
#define G_OP_FLOATS (128 * G_STRIDE)      // 4608 floats per operand tile
#define G_STAGE_FLOATS (2 * G_OP_FLOATS)  // A + B
#define G_SMEM_BYTES (2 * G_STAGE_FLOATS * 4)  // 2 stages = 73728 B

__global__ __launch_bounds__(256, 2) void gemm_tc_kernel(
    const float* __restrict__ A, const float* __restrict__ WT,
    const float* __restrict__ bias, float* __restrict__ C)
{
    extern __shared__ float smf[];
    const uint32_t smem_base = smem_u32(smf);

    const int t    = threadIdx.x;
    const int wid  = t >> 5;
    const int lane = t & 31;
    const int g    = lane >> 2;   // group 0..7
    const int tid4 = lane & 3;    // 0..3
    const int wm   = wid >> 2;    // 0..1 (m: 64 rows each)
    const int wn   = wid & 3;     // 0..3 (n: 32 cols each)
    const int m0 = blockIdx.y * 128;
    const int n0 = blockIdx.x * 128;

    float acc[4][4][4];
    #pragma unroll
    for (int mf = 0; mf < 4; mf++)
        #pragma unroll
        for (int nf = 0; nf < 4; nf++)
            #pragma unroll
            for (int r = 0; r < 4; r++) acc[mf][nf][r] = 0.f;

    // stage load: 1024 float4 units; u = t + i*256, row = u>>3, c4 = u&7
    auto load_stage = [&](int s, int k0) {
        const uint32_t aB = smem_base + (uint32_t)s * G_STAGE_FLOATS * 4;
        const uint32_t bB = aB + G_OP_FLOATS * 4;
        #pragma unroll
        for (int i = 0; i < 4; i++) {
            int u = t + i * 256;
            int row = u >> 3, c4 = u & 7;
            uint32_t off = (uint32_t)(row * G_STRIDE + c4 * 4) * 4;
            CP_ASYNC16(aB + off, A + (size_t)(m0 + row) * Dmod + k0 + c4 * 4);
        }
        #pragma unroll
        for (int i = 0; i < 4; i++) {
            int u = t + i * 256;
            int row = u >> 3, c4 = u & 7;
            uint32_t off = (uint32_t)(row * G_STRIDE + c4 * 4) * 4;
            CP_ASYNC16(bB + off, WT + (size_t)(n0 + row) * Dmod + k0 + c4 * 4);
        }
    };

    load_stage(0, 0);
    CP_COMMIT();
    load_stage(1, G_BK);
    CP_COMMIT();

    for (int k = 0; k < G_NK; k++) {
        const int s = k & 1;
        CP_WAIT(1);
        __syncthreads();

        const float* sA = smf + (size_t)s * G_STAGE_FLOATS;
        const float* sB = sA + G_OP_FLOATS;

        #pragma unroll
        for (int ks = 0; ks < 4; ks++) {
            const int kc = ks * 8 + tid4;
            uint32_t af[4][4], bf[4][2];
            #pragma unroll
            for (int mf = 0; mf < 4; mf++) {
                const int r0 = wm * 64 + mf * 16;
                af[mf][0] = f2tf32(sA[(r0 + g)     * G_STRIDE + kc]);
                af[mf][1] = f2tf32(sA[(r0 + g + 8) * G_STRIDE + kc]);
                af[mf][2] = f2tf32(sA[(r0 + g)     * G_STRIDE + kc + 4]);
                af[mf][3] = f2tf32(sA[(r0 + g + 8) * G_STRIDE + kc + 4]);
            }
            #pragma unroll
            for (int nf = 0; nf < 4; nf++) {
                const int c0 = wn * 32 + nf * 8;
                bf[nf][0] = f2tf32(sB[(c0 + g) * G_STRIDE + kc]);
                bf[nf][1] = f2tf32(sB[(c0 + g) * G_STRIDE + kc + 4]);
            }
            #pragma unroll
            for (int mf = 0; mf < 4; mf++)
                #pragma unroll
                for (int nf = 0; nf < 4; nf++)
                    mma_tf32(acc[mf][nf], af[mf], bf[nf]);
        }

        __syncthreads();
        if (k + 2 < G_NK) load_stage(s, (k + 2) * G_BK);
        CP_COMMIT();
    }

    // Epilogue: C fragment (row g / g+8, col 2*tid4 / +1) + bias
    #pragma unroll
    for (int mf = 0; mf < 4; mf++) {
        const int r0 = m0 + wm * 64 + mf * 16 + g;
        #pragma unroll
        for (int nf = 0; nf < 4; nf++) {
            const int c0 = n0 + wn * 32 + nf * 8 + 2 * tid4;
            const float b0 = bias[c0], b1 = bias[c0 + 1];
            float2 v0 = make_float2(acc[mf][nf][0] + b0, acc[mf][nf][1] + b1);
            float2 v1 = make_float2(acc[mf][nf][2] + b0, acc[mf][nf][3] + b1);
            *(float2*)(C + (size_t)r0 * Dmod + c0)       = v0;
            *(float2*)(C + (size_t)(r0 + 8) * Dmod + c0) = v1;
        }
    }
}

// ---------------------------------------------------------------------------
// Fused causal flash attention (fp32, online softmax) — unchanged (passed R1).
// ---------------------------------------------------------------------------
#define FA_SMEM_FLOATS (128 * 65 + 128 * 65 + 64 * 128 + 64 * 65)

__global__ __launch_bounds__(256) void fa_kernel(
    const float* __restrict__ Q, const float* __restrict__ K,
    const float* __restrict__ V, float* __restrict__ O)
{
    extern __shared__ float sm[];
    float* sQt = sm;                   // [128][65]
    float* sKt = sQt + 128 * 65;       // [128][65]
    float* sV  = sKt + 128 * 65;       // [64][128]
    float* sP  = sV + 64 * 128;        // [64][65]
    float4* sV4 = (float4*)sV;

    const int qb = blockIdx.x;
    const int h  = blockIdx.y;
    const int b  = blockIdx.z;
    const int t  = threadIdx.x;
    const int tx = t & 15;
    const int ty = t >> 4;
    const int q0 = qb * 64;

    const size_t bh_off = (size_t)b * Sseq * Dmod + (size_t)h * DKk;
    const float* Qb = Q + bh_off + (size_t)q0 * Dmod;

    #pragma unroll
    for (int i = 0; i < 8; i++) {
        int idx  = t + i * 256;
        int row  = idx >> 5;
        int colb = idx & 31;
        float4 v4 = *(const float4*)(Qb + (size_t)row * Dmod + colb * 4);
        int d = colb * 4;
        sQt[(d + 0) * 65 + row] = v4.x;
        sQt[(d + 1) * 65 + row] = v4.y;
        sQt[(d + 2) * 65 + row] = v4.z;
        sQt[(d + 3) * 65 + row] = v4.w;
    }

    float m_i[4], l_i[4];
    float o_acc[4][8];
    #pragma unroll
    for (int ii = 0; ii < 4; ii++) {
        m_i[ii] = -1e30f;
        l_i[ii] = 0.f;
        #pragma unroll
        for (int jj = 0; jj < 8; jj++) o_acc[ii][jj] = 0.f;
    }
    __syncthreads();

    const float scale = 0.088388347648318447f;

    for (int kb = 0; kb <= qb; kb++) {
        const int kv0 = kb * 64;
        const float* Kb = K + bh_off + (size_t)kv0 * Dmod;
        const float* Vb = V + bh_off + (size_t)kv0 * Dmod;

        #pragma unroll
        for (int i = 0; i < 8; i++) {
            int idx  = t + i * 256;
            int row  = idx >> 5;
            int colb = idx & 31;
            float4 v4 = *(const float4*)(Kb + (size_t)row * Dmod + colb * 4);
            int d = colb * 4;
            sKt[(d + 0) * 65 + row] = v4.x;
            sKt[(d + 1) * 65 + row] = v4.y;
            sKt[(d + 2) * 65 + row] = v4.z;
            sKt[(d + 3) * 65 + row] = v4.w;
        }
        #pragma unroll
        for (int i = 0; i < 8; i++) {
            int idx  = t + i * 256;
            int row  = idx >> 5;
            int colb = idx & 31;
            sV4[row * 32 + colb] =
                *(const float4*)(Vb + (size_t)row * Dmod + colb * 4);
        }
        __syncthreads();

        float acc[4][4];
        #pragma unroll
        for (int ii = 0; ii < 4; ii++)
            #pragma unroll
            for (int jj = 0; jj < 4; jj++) acc[ii][jj] = 0.f;

        #pragma unroll 4
        for (int d = 0; d < 128; d++) {
            float a0 = sQt[d * 65 + ty];
            float a1 = sQt[d * 65 + ty + 16];
            float a2 = sQt[d * 65 + ty + 32];
            float a3 = sQt[d * 65 + ty + 48];
            float b0 = sKt[d * 65 + tx];
            float b1 = sKt[d * 65 + tx + 16];
            float b2 = sKt[d * 65 + tx + 32];
            float b3 = sKt[d * 65 + tx + 48];
            acc[0][0] = fmaf(a0, b0, acc[0][0]);
            acc[0][1] = fmaf(a0, b1, acc[0][1]);
            acc[0][2] = fmaf(a0, b2, acc[0][2]);
            acc[0][3] = fmaf(a0, b3, acc[0][3]);
            acc[1][0] = fmaf(a1, b0, acc[1][0]);
            acc[1][1] = fmaf(a1, b1, acc[1][1]);
            acc[1][2] = fmaf(a1, b2, acc[1][2]);
            acc[1][3] = fmaf(a1, b3, acc[1][3]);
            acc[2][0] = fmaf(a2, b0, acc[2][0]);
            acc[2][1] = fmaf(a2, b1, acc[2][1]);
            acc[2][2] = fmaf(a2, b2, acc[2][2]);
            acc[2][3] = fmaf(a2, b3, acc[2][3]);
            acc[3][0] = fmaf(a3, b0, acc[3][0]);
            acc[3][1] = fmaf(a3, b1, acc[3][1]);
            acc[3][2] = fmaf(a3, b2, acc[3][2]);
            acc[3][3] = fmaf(a3, b3, acc[3][3]);
        }

        #pragma unroll
        for (int ii = 0; ii < 4; ii++) {
            const int qrow = q0 + ty + 16 * ii;
            float s[4];
            float rmax = -1e30f;
            #pragma unroll
            for (int jj = 0; jj < 4; jj++) {
                int kcol = kv0 + tx + 16 * jj;
                float v = acc[ii][jj] * scale;
                if (kcol > qrow) v = -1e30f;
                s[jj] = v;
                rmax = fmaxf(rmax, v);
            }
            rmax = fmaxf(rmax, __shfl_xor_sync(0xFFFFFFFFu, rmax, 8));
            rmax = fmaxf(rmax, __shfl_xor_sync(0xFFFFFFFFu, rmax, 4));
            rmax = fmaxf(rmax, __shfl_xor_sync(0xFFFFFFFFu, rmax, 2));
            rmax = fmaxf(rmax, __shfl_xor_sync(0xFFFFFFFFu, rmax, 1));

            float m_new = fmaxf(m_i[ii], rmax);
            float corr  = __expf(m_i[ii] - m_new);
            float psum  = 0.f;
            #pragma unroll
            for (int jj = 0; jj < 4; jj++) {
                float p = __expf(s[jj] - m_new);
                sP[(ty + 16 * ii) * 65 + tx + 16 * jj] = p;
                psum += p;
            }
            psum += __shfl_xor_sync(0xFFFFFFFFu, psum, 8);
            psum += __shfl_xor_sync(0xFFFFFFFFu, psum, 4);
            psum += __shfl_xor_sync(0xFFFFFFFFu, psum, 2);
            psum += __shfl_xor_sync(0xFFFFFFFFu, psum, 1);

            l_i[ii] = l_i[ii] * corr + psum;
            m_i[ii] = m_new;
            #pragma unroll
            for (int jj = 0; jj < 8; jj++) o_acc[ii][jj] *= corr;
        }
        __syncthreads();

        #pragma unroll 4
        for (int kk = 0; kk < 64; kk++) {
            float4 v0 = sV4[kk * 32 + tx * 2];
            float4 v1 = sV4[kk * 32 + tx * 2 + 1];
            #pragma unroll
            for (int ii = 0; ii < 4; ii++) {
                float p = sP[(ty + 16 * ii) * 65 + kk];
                o_acc[ii][0] = fmaf(p, v0.x, o_acc[ii][0]);
                o_acc[ii][1] = fmaf(p, v0.y, o_acc[ii][1]);
                o_acc[ii][2] = fmaf(p, v0.z, o_acc[ii][2]);
                o_acc[ii][3] = fmaf(p, v0.w, o_acc[ii][3]);
                o_acc[ii][4] = fmaf(p, v1.x, o_acc[ii][4]);
                o_acc[ii][5] = fmaf(p, v1.y, o_acc[ii][5]);
                o_acc[ii][6] = fmaf(p, v1.z, o_acc[ii][6]);
                o_acc[ii][7] = fmaf(p, v1.w, o_acc[ii][7]);
            }
        }
        __syncthreads();
    }

    float* Ob = O + bh_off + (size_t)q0 * Dmod;
    #pragma unroll
    for (int ii = 0; ii < 4; ii++) {
        float inv = 1.0f / l_i[ii];
        int row = ty + 16 * ii;
        float4 r0 = make_float4(o_acc[ii][0] * inv, o_acc[ii][1] * inv,
                                o_acc[ii][2] * inv, o_acc[ii][3] * inv);
        float4 r1 = make_float4(o_acc[ii][4] * inv, o_acc[ii][5] * inv,
                                o_acc[ii][6] * inv, o_acc[ii][7] * inv);
        *(float4*)(Ob + (size_t)row * Dmod + tx * 8)     = r0;
        *(float4*)(Ob + (size_t)row * Dmod + tx * 8 + 4) = r1;
    }
}

// ---------------------------------------------------------------------------
// kernel_launch
// ---------------------------------------------------------------------------
extern "C" void kernel_launch(void* const* d_in, const int* in_sizes, int n_in,
                              void* d_out, int out_size)
{
    const float* queries = (const float*)d_in[0];
    const float* keys    = (const float*)d_in[1];
    const float* values  = (const float*)d_in[2];
    const float* Wq      = (const float*)d_in[3];
    const float* bq      = (const float*)d_in[4];
    const float* Wlk     = (const float*)d_in[5];
    const float* blk     = (const float*)d_in[6];
    const float* Wlv     = (const float*)d_in[7];
    const float* blv     = (const float*)d_in[8];
    const float* Wkr     = (const float*)d_in[9];
    const float* bkr     = (const float*)d_in[10];
    const float* Wvr     = (const float*)d_in[11];
    const float* bvr     = (const float*)d_in[12];
    const float* Wo      = (const float*)d_in[13];
    const float* bo      = (const float*)d_in[14];
    float* out = (float*)d_out;

    float *Q, *K, *V, *O, *Wtmp, *WqT, *WkT, *WvT, *WoT, *bk, *bv;
    cudaGetSymbolAddress((void**)&Q,    g_Q);
    cudaGetSymbolAddress((void**)&K,    g_K);
    cudaGetSymbolAddress((void**)&V,    g_V);
    cudaGetSymbolAddress((void**)&O,    g_O);
    cudaGetSymbolAddress((void**)&Wtmp, g_Wtmp);
    cudaGetSymbolAddress((void**)&WqT,  g_WqT);
    cudaGetSymbolAddress((void**)&WkT,  g_WkT);
    cudaGetSymbolAddress((void**)&WvT,  g_WvT);
    cudaGetSymbolAddress((void**)&WoT,  g_WoT);
    cudaGetSymbolAddress((void**)&bk,   g_bk);
    cudaGetSymbolAddress((void**)&bv,   g_bv);

    cudaFuncSetAttribute(gemm_tc_kernel,
                         cudaFuncAttributeMaxDynamicSharedMemorySize, G_SMEM_BYTES);
    size_t fa_smem = (size_t)FA_SMEM_FLOATS * sizeof(float);
    cudaFuncSetAttribute(fa_kernel, cudaFuncAttributeMaxDynamicSharedMemorySize,
                         (int)fa_smem);

    const dim3 tgrid(Dmod / 32, Dmod / 32);
    const dim3 ggrid(Dmod / 128, Mrows / 128);

    // Launch order keeps launch #6 = K-projection GEMM (ncu -s 5 -c 1 target)
    transpose_kernel<<<tgrid, 256>>>(Wq, WqT);                                   // 1
    gemm_tc_kernel<<<ggrid, 256, G_SMEM_BYTES>>>(queries, WqT, bq, Q);           // 2

    fold_w_kernel<<<dim3(Dmod, Hh), 128>>>(Wlk, Wkr, Wtmp);                      // 3
    fold_b_kernel<<<Hh, 128>>>(blk, Wkr, bkr, bk);                               // 4
    transpose_kernel<<<tgrid, 256>>>(Wtmp, WkT);                                 // 5
    gemm_tc_kernel<<<ggrid, 256, G_SMEM_BYTES>>>(keys, WkT, bk, K);              // 6

    fold_w_kernel<<<dim3(Dmod, Hh), 128>>>(Wlv, Wvr, Wtmp);                      // 7
    fold_b_kernel<<<Hh, 128>>>(blv, Wvr, bvr, bv);                               // 8
    transpose_kernel<<<tgrid, 256>>>(Wtmp, WvT);                                 // 9
    gemm_tc_kernel<<<ggrid, 256, G_SMEM_BYTES>>>(values, WvT, bv, V);            // 10

    fa_kernel<<<dim3(Sseq / 64, Hh, Bsz), 256, fa_smem>>>(Q, K, V, O);           // 11

    transpose_kernel<<<tgrid, 256>>>(Wo, WoT);                                   // 12
    gemm_tc_kernel<<<ggrid, 256, G_SMEM_BYTES>>>(O, WoT, bo, out);               // 13
}

// round 4
// speedup vs baseline: 3.6607x; 1.7581x over previous
#include <cuda_runtime.h>
#include <cuda_bf16.h>
#include <math.h>
#include <cstdint>

// Problem constants
#define Bsz   2
#define Sseq  2048
#define Dmod  2048
#define Hh    16
#define DKk   128
#define Ll    64
#define Mrows (Bsz * Sseq)   // 4096

// ---------------------------------------------------------------------------
// Device scratch
// ---------------------------------------------------------------------------
__device__ float g_Q  [(size_t)Mrows * Dmod];
__device__ float g_K  [(size_t)Mrows * Dmod];
__device__ float g_VT [(size_t)Mrows * Dmod];   // [b, h, d, s]
__device__ float g_O  [(size_t)Mrows * Dmod];
__device__ float g_Wtmp[(size_t)Dmod * Dmod];
__device__ float g_WqT[(size_t)Dmod * Dmod];
__device__ float g_WkT[(size_t)Dmod * Dmod];
__device__ float g_WvT[(size_t)Dmod * Dmod];
__device__ float g_WoT[(size_t)Dmod * Dmod];
__device__ float g_bk[Dmod];
__device__ float g_bv[Dmod];

// ---------------------------------------------------------------------------
// Helpers
// ---------------------------------------------------------------------------
__device__ __forceinline__ uint32_t smem_u32(const void* p) {
    uint32_t a;
    asm("{ .reg .u64 t; cvta.to.shared.u64 t, %1; cvt.u32.u64 %0, t; }"
        : "=r"(a) : "l"(p));
    return a;
}

#define CP_ASYNC16(dst, src) \
    asm volatile("cp.async.cg.shared.global [%0], [%1], 16;" \
        :: "r"((uint32_t)(dst)), "l"(src) : "memory")
#define CP_COMMIT() asm volatile("cp.async.commit_group;" ::: "memory")
#define CP_WAIT(n)  asm volatile("cp.async.wait_group %0;" :: "n"(n) : "memory")

__device__ __forceinline__ uint32_t f2tf32(float x) {
    uint32_t r;
    asm("cvt.rna.tf32.f32 %0, %1;" : "=r"(r) : "f"(x));
    return r;
}

__device__ __forceinline__ void mma_tf32(float* c, const uint32_t* a, const uint32_t* b) {
    asm volatile(
        "mma.sync.aligned.m16n8k8.row.col.f32.tf32.tf32.f32 "
        "{%0,%1,%2,%3}, {%4,%5,%6,%7}, {%8,%9}, {%0,%1,%2,%3};"
        : "+f"(c[0]), "+f"(c[1]), "+f"(c[2]), "+f"(c[3])
        : "r"(a[0]), "r"(a[1]), "r"(a[2]), "r"(a[3]), "r"(b[0]), "r"(b[1]));
}

// bf16 m16n8k16: D = A(16x16) @ B(16x8, col) + D
__device__ __forceinline__ void mma_bf16(float* c, const uint32_t* a,
                                         uint32_t b0, uint32_t b1) {
    asm volatile(
        "mma.sync.aligned.m16n8k16.row.col.f32.bf16.bf16.f32 "
        "{%0,%1,%2,%3}, {%4,%5,%6,%7}, {%8,%9}, {%0,%1,%2,%3};"
        : "+f"(c[0]), "+f"(c[1]), "+f"(c[2]), "+f"(c[3])
        : "r"(a[0]), "r"(a[1]), "r"(a[2]), "r"(a[3]), "r"(b0), "r"(b1));
}

// pack two floats into bf16x2: e0 -> lower half (first k-element), e1 -> upper
__device__ __forceinline__ uint32_t packbf(float e0, float e1) {
    uint32_t r;
    asm("cvt.rn.bf16x2.f32 %0, %1, %2;" : "=r"(r) : "f"(e1), "f"(e0));
    return r;
}

// split (e0, e1) into bf16x2 hi + bf16x2 lo (residual)
__device__ __forceinline__ void split2(float e0, float e1,
                                       uint32_t& hi, uint32_t& lo) {
    hi = packbf(e0, e1);
    float r0 = e0 - __uint_as_float(hi << 16);
    float r1 = e1 - __uint_as_float(hi & 0xFFFF0000u);
    lo = packbf(r0, r1);
}

__device__ __forceinline__ float ex2(float x) {
    float y;
    asm("ex2.approx.ftz.f32 %0, %1;" : "=f"(y) : "f"(x));
    return y;
}

// ---------------------------------------------------------------------------
// Weight fold
// ---------------------------------------------------------------------------
__global__ __launch_bounds__(128) void fold_w_kernel(
    const float* __restrict__ Wl, const float* __restrict__ Wr,
    float* __restrict__ Weff)
{
    const int d = blockIdx.x;
    const int h = blockIdx.y;
    const int c = threadIdx.x;
    __shared__ float sl[Ll];
    if (c < Ll) sl[c] = Wl[(size_t)d * (Hh * Ll) + h * Ll + c];
    __syncthreads();
    float acc = 0.f;
    #pragma unroll 16
    for (int l = 0; l < Ll; l++)
        acc += sl[l] * Wr[l * DKk + c];
    Weff[(size_t)d * Dmod + h * DKk + c] = acc;
}

__global__ __launch_bounds__(128) void fold_b_kernel(
    const float* __restrict__ bl, const float* __restrict__ Wr,
    const float* __restrict__ br, float* __restrict__ beff)
{
    const int h = blockIdx.x;
    const int c = threadIdx.x;
    float acc = br[c];
    #pragma unroll 16
    for (int l = 0; l < Ll; l++)
        acc += bl[h * Ll + l] * Wr[l * DKk + c];
    beff[h * DKk + c] = acc;
}

// ---------------------------------------------------------------------------
// 32x32 tiled transpose
// ---------------------------------------------------------------------------
__global__ __launch_bounds__(256) void transpose_kernel(
    const float* __restrict__ in, float* __restrict__ out)
{
    __shared__ float tile[32][33];
    const int bx = blockIdx.x * 32;
    const int by = blockIdx.y * 32;
    const int tx = threadIdx.x & 31;
    const int ty = threadIdx.x >> 5;
    #pragma unroll
    for (int i = 0; i < 32; i += 8)
        tile[ty + i][tx] = in[(size_t)(by + ty + i) * Dmod + bx + tx];
    __syncthreads();
    #pragma unroll
    for (int i = 0; i < 32; i += 8)
        out[(size_t)(bx + ty + i) * Dmod + by + tx] = tile[tx][ty + i];
}

// ---------------------------------------------------------------------------
// Tensor-core tf32 GEMM:  C[M,N] = A[M,K] @ WT[N,K]^T + bias[N]
// TRANS_OUT=true writes C transposed into [b, h, d, s] layout (for V).
// ---------------------------------------------------------------------------
#define G_BK 32
#define G_NK (Dmod / G_BK)
#define G_STRIDE 36
#define G_OP_FLOATS (128 * G_STRIDE)
#define G_STAGE_FLOATS (2 * G_OP_FLOATS)
#define G_SMEM_BYTES (2 * G_STAGE_FLOATS * 4)

template<bool TRANS_OUT>
__global__ __launch_bounds__(256, 2) void gemm_tc_kernel(
    const float* __restrict__ A, const float* __restrict__ WT,
    const float* __restrict__ bias, float* __restrict__ C)
{
    extern __shared__ float smf[];
    const uint32_t smem_base = smem_u32(smf);

    const int t    = threadIdx.x;
    const int wid  = t >> 5;
    const int lane = t & 31;
    const int g    = lane >> 2;
    const int tid4 = lane & 3;
    const int wm   = wid >> 2;
    const int wn   = wid & 3;
    const int m0 = blockIdx.y * 128;
    const int n0 = blockIdx.x * 128;

    float acc[4][4][4];
    #pragma unroll
    for (int mf = 0; mf < 4; mf++)
        #pragma unroll
        for (int nf = 0; nf < 4; nf++)
            #pragma unroll
            for (int r = 0; r < 4; r++) acc[mf][nf][r] = 0.f;

    auto load_stage = [&](int s, int k0) {
        const uint32_t aB = smem_base + (uint32_t)s * G_STAGE_FLOATS * 4;
        const uint32_t bB = aB + G_OP_FLOATS * 4;
        #pragma unroll
        for (int i = 0; i < 4; i++) {
            int u = t + i * 256;
            int row = u >> 3, c4 = u & 7;
            uint32_t off = (uint32_t)(row * G_STRIDE + c4 * 4) * 4;
            CP_ASYNC16(aB + off, A + (size_t)(m0 + row) * Dmod + k0 + c4 * 4);
        }
        #pragma unroll
        for (int i = 0; i < 4; i++) {
            int u = t + i * 256;
            int row = u >> 3, c4 = u & 7;
            uint32_t off = (uint32_t)(row * G_STRIDE + c4 * 4) * 4;
            CP_ASYNC16(bB + off, WT + (size_t)(n0 + row) * Dmod + k0 + c4 * 4);
        }
    };

    load_stage(0, 0);
    CP_COMMIT();
    load_stage(1, G_BK);
    CP_COMMIT();

    for (int k = 0; k < G_NK; k++) {
        const int s = k & 1;
        CP_WAIT(1);
        __syncthreads();

        const float* sA = smf + (size_t)s * G_STAGE_FLOATS;
        const float* sB = sA + G_OP_FLOATS;

        #pragma unroll
        for (int ks = 0; ks < 4; ks++) {
            const int kc = ks * 8 + tid4;
            uint32_t af[4][4], bf[4][2];
            #pragma unroll
            for (int mf = 0; mf < 4; mf++) {
                const int r0 = wm * 64 + mf * 16;
                af[mf][0] = f2tf32(sA[(r0 + g)     * G_STRIDE + kc]);
                af[mf][1] = f2tf32(sA[(r0 + g + 8) * G_STRIDE + kc]);
                af[mf][2] = f2tf32(sA[(r0 + g)     * G_STRIDE + kc + 4]);
                af[mf][3] = f2tf32(sA[(r0 + g + 8) * G_STRIDE + kc + 4]);
            }
            #pragma unroll
            for (int nf = 0; nf < 4; nf++) {
                const int c0 = wn * 32 + nf * 8;
                bf[nf][0] = f2tf32(sB[(c0 + g) * G_STRIDE + kc]);
                bf[nf][1] = f2tf32(sB[(c0 + g) * G_STRIDE + kc + 4]);
            }
            #pragma unroll
            for (int mf = 0; mf < 4; mf++)
                #pragma unroll
                for (int nf = 0; nf < 4; nf++)
                    mma_tf32(acc[mf][nf], af[mf], bf[nf]);
        }

        __syncthreads();
        if (k + 2 < G_NK) load_stage(s, (k + 2) * G_BK);
        CP_COMMIT();
    }

    #pragma unroll
    for (int mf = 0; mf < 4; mf++) {
        const int r0 = m0 + wm * 64 + mf * 16 + g;
        #pragma unroll
        for (int nf = 0; nf < 4; nf++) {
            const int c0 = n0 + wn * 32 + nf * 8 + 2 * tid4;
            const float b0 = bias[c0], b1 = bias[c0 + 1];
            if (!TRANS_OUT) {
                float2 v0 = make_float2(acc[mf][nf][0] + b0, acc[mf][nf][1] + b1);
                float2 v1 = make_float2(acc[mf][nf][2] + b0, acc[mf][nf][3] + b1);
                *(float2*)(C + (size_t)r0 * Dmod + c0)       = v0;
                *(float2*)(C + (size_t)(r0 + 8) * Dmod + c0) = v1;
            } else {
                // out[b][h][d][s] = C[r][c]; r = b*2048+s, c = h*128+d
                const int bb = r0 >> 11, s0 = r0 & 2047;
                const int hh = c0 >> 7,  dd = c0 & 127;
                float* base = C + ((size_t)(bb * Hh + hh) * DKk + dd) * Sseq;
                base[s0]            = acc[mf][nf][0] + b0;
                base[Sseq + s0]     = acc[mf][nf][1] + b1;
                base[s0 + 8]        = acc[mf][nf][2] + b0;
                base[Sseq + s0 + 8] = acc[mf][nf][3] + b1;
            }
        }
    }
}

// ---------------------------------------------------------------------------
// Tensor-core causal flash attention, bf16 hi/lo split (x3 MMA) both GEMMs.
// CTA = 128 q rows of one (b,h); 8 warps, each owns m16. kv tile = 64.
// Q frags preloaded in regs (pre-scaled). K smem [kv][d] hi/lo planes,
// V smem [d][kv] hi/lo planes (from pre-transposed VT global).
// ---------------------------------------------------------------------------
#define KROWW 68   // K plane row stride in uint32 words (136 bf16)
#define VROWW 36   // VT plane row stride in uint32 words (72 bf16)
#define FA_SMEM_WORDS (2 * 64 * KROWW + 2 * 128 * VROWW)   // 17920 words
#define FA_SMEM_BYTES (FA_SMEM_WORDS * 4)                  // 71680 B

__global__ __launch_bounds__(256, 1) void fa_tc_kernel(
    const float* __restrict__ Q, const float* __restrict__ K,
    const float* __restrict__ VT, float* __restrict__ O)
{
    extern __shared__ uint32_t su[];
    uint32_t* Khi = su;                      // 64 x 68
    uint32_t* Klo = su + 64 * KROWW;
    uint32_t* Vhi = su + 2 * 64 * KROWW;     // 128 x 36
    uint32_t* Vlo = Vhi + 128 * VROWW;

    const int qb = (int)gridDim.x - 1 - (int)blockIdx.x;  // heavy blocks first
    const int h  = blockIdx.y;
    const int b  = blockIdx.z;
    const int t  = threadIdx.x;
    const int w  = t >> 5;
    const int lane = t & 31;
    const int g  = lane >> 2;
    const int t4 = lane & 3;
    const int q0 = qb * 128;

    const size_t bh_off = (size_t)b * Sseq * Dmod + (size_t)h * DKk;
    const float* Kg  = K + bh_off;
    const float* VTg = VT + (size_t)(b * Hh + h) * DKk * Sseq;

    // Preload Q fragments (pre-scaled to base-2 softmax domain), split hi/lo
    const float qscale = 0.088388347648318447f * 1.4426950408889634f;
    uint32_t qhi[8][4], qlo[8][4];
    {
        const float* Qw = Q + bh_off + (size_t)(q0 + w * 16) * Dmod;
        #pragma unroll
        for (int ks = 0; ks < 8; ks++) {
            const int d0 = ks * 16 + 2 * t4;
            float2 x0 = *(const float2*)(Qw + (size_t)g * Dmod + d0);
            float2 x1 = *(const float2*)(Qw + (size_t)(g + 8) * Dmod + d0);
            float2 x2 = *(const float2*)(Qw + (size_t)g * Dmod + d0 + 8);
            float2 x3 = *(const float2*)(Qw + (size_t)(g + 8) * Dmod + d0 + 8);
            split2(x0.x * qscale, x0.y * qscale, qhi[ks][0], qlo[ks][0]);
            split2(x1.x * qscale, x1.y * qscale, qhi[ks][1], qlo[ks][1]);
            split2(x2.x * qscale, x2.y * qscale, qhi[ks][2], qlo[ks][2]);
            split2(x3.x * qscale, x3.y * qscale, qhi[ks][3], qlo[ks][3]);
        }
    }

    float oacc[16][4];
    #pragma unroll
    for (int nf = 0; nf < 16; nf++)
        #pragma unroll
        for (int r = 0; r < 4; r++) oacc[nf][r] = 0.f;

    float m0 = -1e30f, m1 = -1e30f, l0 = 0.f, l1 = 0.f;
    const int row0 = q0 + w * 16 + g;
    const int row1 = row0 + 8;

    const int ntiles = 2 * qb + 2;
    for (int kt = 0; kt < ntiles; kt++) {
        const int kv0 = kt * 64;

        // ---- load K tile [64 kv][128 d] -> hi/lo planes ----
        #pragma unroll
        for (int i = 0; i < 8; i++) {
            int u = t + i * 256;
            int c4 = u & 31, kv = u >> 5;
            float4 x = *(const float4*)(Kg + (size_t)(kv0 + kv) * Dmod + 4 * c4);
            uint32_t h0, e0, h1, e1;
            split2(x.x, x.y, h0, e0);
            split2(x.z, x.w, h1, e1);
            *(uint2*)&Khi[kv * KROWW + 2 * c4] = make_uint2(h0, h1);
            *(uint2*)&Klo[kv * KROWW + 2 * c4] = make_uint2(e0, e1);
        }
        // ---- load V tile [128 d][64 kv] from VT global ----
        #pragma unroll
        for (int i = 0; i < 8; i++) {
            int u = t + i * 256;
            int c4 = u & 15, d = u >> 4;
            float4 x = *(const float4*)(VTg + (size_t)d * Sseq + kv0 + 4 * c4);
            uint32_t h0, e0, h1, e1;
            split2(x.x, x.y, h0, e0);
            split2(x.z, x.w, h1, e1);
            *(uint2*)&Vhi[d * VROWW + 2 * c4] = make_uint2(h0, h1);
            *(uint2*)&Vlo[d * VROWW + 2 * c4] = make_uint2(e0, e1);
        }
        __syncthreads();

        // ---- QK^T: acc[nf] covers n = kv (nf*8..), rows row0/row1 ----
        float acc[8][4];
        #pragma unroll
        for (int nf = 0; nf < 8; nf++)
            #pragma unroll
            for (int r = 0; r < 4; r++) acc[nf][r] = 0.f;

        #pragma unroll
        for (int ks = 0; ks < 8; ks++) {
            #pragma unroll
            for (int nf = 0; nf < 8; nf++) {
                const int r = (nf * 8 + g) * KROWW + 8 * ks + t4;
                uint32_t bh0 = Khi[r], bh1 = Khi[r + 4];
                uint32_t bl0 = Klo[r], bl1 = Klo[r + 4];
                mma_bf16(acc[nf], qhi[ks], bh0, bh1);
                mma_bf16(acc[nf], qhi[ks], bl0, bl1);
                mma_bf16(acc[nf], qlo[ks], bh0, bh1);
            }
        }

        // ---- causal mask (only diagonal tiles) ----
        if (kv0 + 63 > q0) {
            #pragma unroll
            for (int nf = 0; nf < 8; nf++) {
                const int c = kv0 + nf * 8 + 2 * t4;
                if (c     > row0) acc[nf][0] = -1e30f;
                if (c + 1 > row0) acc[nf][1] = -1e30f;
                if (c     > row1) acc[nf][2] = -1e30f;
                if (c + 1 > row1) acc[nf][3] = -1e30f;
            }
        }

        // ---- online softmax (base-2 domain; scores pre-scaled via Q) ----
        float mx0 = -1e30f, mx1 = -1e30f;
        #pragma unroll
        for (int nf = 0; nf < 8; nf++) {
            mx0 = fmaxf(mx0, fmaxf(acc[nf][0], acc[nf][1]));
            mx1 = fmaxf(mx1, fmaxf(acc[nf][2], acc[nf][3]));
        }
        mx0 = fmaxf(mx0, __shfl_xor_sync(0xFFFFFFFFu, mx0, 1));
        mx0 = fmaxf(mx0, __shfl_xor_sync(0xFFFFFFFFu, mx0, 2));
        mx1 = fmaxf(mx1, __shfl_xor_sync(0xFFFFFFFFu, mx1, 1));
        mx1 = fmaxf(mx1, __shfl_xor_sync(0xFFFFFFFFu, mx1, 2));

        const float mn0 = fmaxf(m0, mx0);
        const float mn1 = fmaxf(m1, mx1);
        const float cr0 = ex2(m0 - mn0);
        const float cr1 = ex2(m1 - mn1);

        float ps0 = 0.f, ps1 = 0.f;
        #pragma unroll
        for (int nf = 0; nf < 8; nf++) {
            acc[nf][0] = ex2(acc[nf][0] - mn0);
            acc[nf][1] = ex2(acc[nf][1] - mn0);
            acc[nf][2] = ex2(acc[nf][2] - mn1);
            acc[nf][3] = ex2(acc[nf][3] - mn1);
            ps0 += acc[nf][0] + acc[nf][1];
            ps1 += acc[nf][2] + acc[nf][3];
        }
        ps0 += __shfl_xor_sync(0xFFFFFFFFu, ps0, 1);
        ps0 += __shfl_xor_sync(0xFFFFFFFFu, ps0, 2);
        ps1 += __shfl_xor_sync(0xFFFFFFFFu, ps1, 1);
        ps1 += __shfl_xor_sync(0xFFFFFFFFu, ps1, 2);

        l0 = l0 * cr0 + ps0;
        l1 = l1 * cr1 + ps1;
        m0 = mn0;
        m1 = mn1;

        #pragma unroll
        for (int nf = 0; nf < 16; nf++) {
            oacc[nf][0] *= cr0;
            oacc[nf][1] *= cr0;
            oacc[nf][2] *= cr1;
            oacc[nf][3] *= cr1;
        }

        // ---- P @ V: A = P fragments from QK accumulators (register pack) ----
        #pragma unroll
        for (int ks2 = 0; ks2 < 4; ks2++) {
            uint32_t ahi[4], alo[4];
            split2(acc[2 * ks2][0],     acc[2 * ks2][1],     ahi[0], alo[0]);
            split2(acc[2 * ks2][2],     acc[2 * ks2][3],     ahi[1], alo[1]);
            split2(acc[2 * ks2 + 1][0], acc[2 * ks2 + 1][1], ahi[2], alo[2]);
            split2(acc[2 * ks2 + 1][2], acc[2 * ks2 + 1][3], ahi[3], alo[3]);
            #pragma unroll
            for (int nf = 0; nf < 16; nf++) {
                const int r = (nf * 8 + g) * VROWW + 8 * ks2 + t4;
                uint32_t bh0 = Vhi[r], bh1 = Vhi[r + 4];
                uint32_t bl0 = Vlo[r], bl1 = Vlo[r + 4];
                mma_bf16(oacc[nf], ahi, bh0, bh1);
                mma_bf16(oacc[nf], ahi, bl0, bl1);
                mma_bf16(oacc[nf], alo, bh0, bh1);
            }
        }
        __syncthreads();
    }

    // ---- epilogue: normalize, store O [b, s, h*128+d] ----
    const float inv0 = 1.0f / l0;
    const float inv1 = 1.0f / l1;
    float* Ow = O + bh_off + (size_t)(q0 + w * 16) * Dmod;
    #pragma unroll
    for (int nf = 0; nf < 16; nf++) {
        const int col = nf * 8 + 2 * t4;
        *(float2*)(Ow + (size_t)g * Dmod + col) =
            make_float2(oacc[nf][0] * inv0, oacc[nf][1] * inv0);
        *(float2*)(Ow + (size_t)(g + 8) * Dmod + col) =
            make_float2(oacc[nf][2] * inv1, oacc[nf][3] * inv1);
    }
}

// ---------------------------------------------------------------------------
// kernel_launch
// ---------------------------------------------------------------------------
extern "C" void kernel_launch(void* const* d_in, const int* in_sizes, int n_in,
                              void* d_out, int out_size)
{
    const float* queries = (const float*)d_in[0];
    const float* keys    = (const float*)d_in[1];
    const float* values  = (const float*)d_in[2];
    const float* Wq      = (const float*)d_in[3];
    const float* bq      = (const float*)d_in[4];
    const float* Wlk     = (const float*)d_in[5];
    const float* blk     = (const float*)d_in[6];
    const float* Wlv     = (const float*)d_in[7];
    const float* blv     = (const float*)d_in[8];
    const float* Wkr     = (const float*)d_in[9];
    const float* bkr     = (const float*)d_in[10];
    const float* Wvr     = (const float*)d_in[11];
    const float* bvr     = (const float*)d_in[12];
    const float* Wo      = (const float*)d_in[13];
    const float* bo      = (const float*)d_in[14];
    float* out = (float*)d_out;

    float *Q, *K, *VT, *O, *Wtmp, *WqT, *WkT, *WvT, *WoT, *bk, *bv;
    cudaGetSymbolAddress((void**)&Q,    g_Q);
    cudaGetSymbolAddress((void**)&K,    g_K);
    cudaGetSymbolAddress((void**)&VT,   g_VT);
    cudaGetSymbolAddress((void**)&O,    g_O);
    cudaGetSymbolAddress((void**)&Wtmp, g_Wtmp);
    cudaGetSymbolAddress((void**)&WqT,  g_WqT);
    cudaGetSymbolAddress((void**)&WkT,  g_WkT);
    cudaGetSymbolAddress((void**)&WvT,  g_WvT);
    cudaGetSymbolAddress((void**)&WoT,  g_WoT);
    cudaGetSymbolAddress((void**)&bk,   g_bk);
    cudaGetSymbolAddress((void**)&bv,   g_bv);

    cudaFuncSetAttribute(gemm_tc_kernel<false>,
                         cudaFuncAttributeMaxDynamicSharedMemorySize, G_SMEM_BYTES);
    cudaFuncSetAttribute(gemm_tc_kernel<true>,
                         cudaFuncAttributeMaxDynamicSharedMemorySize, G_SMEM_BYTES);
    cudaFuncSetAttribute(fa_tc_kernel,
                         cudaFuncAttributeMaxDynamicSharedMemorySize, FA_SMEM_BYTES);

    const dim3 tgrid(Dmod / 32, Dmod / 32);
    const dim3 ggrid(Dmod / 128, Mrows / 128);

    transpose_kernel<<<tgrid, 256>>>(Wq, WqT);
    gemm_tc_kernel<false><<<ggrid, 256, G_SMEM_BYTES>>>(queries, WqT, bq, Q);

    fold_w_kernel<<<dim3(Dmod, Hh), 128>>>(Wlk, Wkr, Wtmp);
    fold_b_kernel<<<Hh, 128>>>(blk, Wkr, bkr, bk);
    transpose_kernel<<<tgrid, 256>>>(Wtmp, WkT);
    gemm_tc_kernel<false><<<ggrid, 256, G_SMEM_BYTES>>>(keys, WkT, bk, K);

    fold_w_kernel<<<dim3(Dmod, Hh), 128>>>(Wlv, Wvr, Wtmp);
    fold_b_kernel<<<Hh, 128>>>(blv, Wvr, bvr, bv);
    transpose_kernel<<<tgrid, 256>>>(Wtmp, WvT);
    gemm_tc_kernel<true><<<ggrid, 256, G_SMEM_BYTES>>>(values, WvT, bv, VT);

    fa_tc_kernel<<<dim3(Sseq / 128, Hh, Bsz), 256, FA_SMEM_BYTES>>>(Q, K, VT, O);

    transpose_kernel<<<tgrid, 256>>>(Wo, WoT);
    gemm_tc_kernel<false><<<ggrid, 256, G_SMEM_BYTES>>>(O, WoT, bo, out);
}

// round 5
// speedup vs baseline: 3.9362x; 1.0753x over previous
#include <cuda_runtime.h>
#include <cuda_bf16.h>
#include <math.h>
#include <cstdint>

// Problem constants
#define Bsz   2
#define Sseq  2048
#define Dmod  2048
#define Hh    16
#define DKk   128
#define Ll    64
#define Mrows (Bsz * Sseq)   // 4096

// ---------------------------------------------------------------------------
// Device scratch
// ---------------------------------------------------------------------------
__device__ float g_Q  [(size_t)Mrows * Dmod];
__device__ float g_K  [(size_t)Mrows * Dmod];
__device__ float g_VT [(size_t)Mrows * Dmod];   // [b, h, d, s]
__device__ float g_O  [(size_t)Mrows * Dmod];
__device__ float g_Ar [(size_t)Mrows * Dmod];   // rounded+permuted activations
__device__ float g_Wtmp[(size_t)Dmod * Dmod];
__device__ float g_WqT[(size_t)Dmod * Dmod];
__device__ float g_WkT[(size_t)Dmod * Dmod];
__device__ float g_WvT[(size_t)Dmod * Dmod];
__device__ float g_WoT[(size_t)Dmod * Dmod];
__device__ float g_bk[Dmod];
__device__ float g_bv[Dmod];

// ---------------------------------------------------------------------------
// Helpers
// ---------------------------------------------------------------------------
__device__ __forceinline__ uint32_t smem_u32(const void* p) {
    uint32_t a;
    asm("{ .reg .u64 t; cvta.to.shared.u64 t, %1; cvt.u32.u64 %0, t; }"
        : "=r"(a) : "l"(p));
    return a;
}

#define CP_ASYNC16(dst, src) \
    asm volatile("cp.async.cg.shared.global [%0], [%1], 16;" \
        :: "r"((uint32_t)(dst)), "l"(src) : "memory")
#define CP_COMMIT() asm volatile("cp.async.commit_group;" ::: "memory")
#define CP_WAIT(n)  asm volatile("cp.async.wait_group %0;" :: "n"(n) : "memory")

__device__ __forceinline__ uint32_t f2tf32(float x) {
    uint32_t r;
    asm("cvt.rna.tf32.f32 %0, %1;" : "=r"(r) : "f"(x));
    return r;
}

// k-permutation within 8-element groups: pairs (t4, t4+4) -> adjacent words
__device__ __host__ __forceinline__ int perm8(int w) {
    return (w & ~7) | (((w & 3) << 1) | ((w >> 2) & 1));
}

__device__ __forceinline__ void mma_tf32(float* c, const uint32_t* a, const uint32_t* b) {
    asm volatile(
        "mma.sync.aligned.m16n8k8.row.col.f32.tf32.tf32.f32 "
        "{%0,%1,%2,%3}, {%4,%5,%6,%7}, {%8,%9}, {%0,%1,%2,%3};"
        : "+f"(c[0]), "+f"(c[1]), "+f"(c[2]), "+f"(c[3])
        : "r"(a[0]), "r"(a[1]), "r"(a[2]), "r"(a[3]), "r"(b[0]), "r"(b[1]));
}

__device__ __forceinline__ void mma_bf16(float* c, const uint32_t* a,
                                         uint32_t b0, uint32_t b1) {
    asm volatile(
        "mma.sync.aligned.m16n8k16.row.col.f32.bf16.bf16.f32 "
        "{%0,%1,%2,%3}, {%4,%5,%6,%7}, {%8,%9}, {%0,%1,%2,%3};"
        : "+f"(c[0]), "+f"(c[1]), "+f"(c[2]), "+f"(c[3])
        : "r"(a[0]), "r"(a[1]), "r"(a[2]), "r"(a[3]), "r"(b0), "r"(b1));
}

__device__ __forceinline__ uint32_t packbf(float e0, float e1) {
    uint32_t r;
    asm("cvt.rn.bf16x2.f32 %0, %1, %2;" : "=r"(r) : "f"(e1), "f"(e0));
    return r;
}

__device__ __forceinline__ void split2(float e0, float e1,
                                       uint32_t& hi, uint32_t& lo) {
    hi = packbf(e0, e1);
    float r0 = e0 - __uint_as_float(hi << 16);
    float r1 = e1 - __uint_as_float(hi & 0xFFFF0000u);
    lo = packbf(r0, r1);
}

__device__ __forceinline__ float ex2(float x) {
    float y;
    asm("ex2.approx.ftz.f32 %0, %1;" : "=f"(y) : "f"(x));
    return y;
}

// ---------------------------------------------------------------------------
// Round activations to tf32 (rna) and apply k-permutation. 1 float4 / thread.
// ---------------------------------------------------------------------------
__global__ __launch_bounds__(256) void round_perm_kernel(
    const float* __restrict__ in, float* __restrict__ out)
{
    const size_t i4 = (size_t)blockIdx.x * 256 + threadIdx.x;
    const float4 v = ((const float4*)in)[i4];
    const size_t k = i4 * 4;
    const size_t base = k & ~7ull;
    const int r0 = (int)(k & 7);  // multiple of 4
    out[base + perm8(r0 + 0)] = __uint_as_float(f2tf32(v.x));
    out[base + perm8(r0 + 1)] = __uint_as_float(f2tf32(v.y));
    out[base + perm8(r0 + 2)] = __uint_as_float(f2tf32(v.z));
    out[base + perm8(r0 + 3)] = __uint_as_float(f2tf32(v.w));
}

// ---------------------------------------------------------------------------
// Weight fold (fp32 out; transpose pass rounds+permutes)
// ---------------------------------------------------------------------------
__global__ __launch_bounds__(128) void fold_w_kernel(
    const float* __restrict__ Wl, const float* __restrict__ Wr,
    float* __restrict__ Weff)
{
    const int d = blockIdx.x;
    const int h = blockIdx.y;
    const int c = threadIdx.x;
    __shared__ float sl[Ll];
    if (c < Ll) sl[c] = Wl[(size_t)d * (Hh * Ll) + h * Ll + c];
    __syncthreads();
    float acc = 0.f;
    #pragma unroll 16
    for (int l = 0; l < Ll; l++)
        acc += sl[l] * Wr[l * DKk + c];
    Weff[(size_t)d * Dmod + h * DKk + c] = acc;
}

__global__ __launch_bounds__(128) void fold_b_kernel(
    const float* __restrict__ bl, const float* __restrict__ Wr,
    const float* __restrict__ br, float* __restrict__ beff)
{
    const int h = blockIdx.x;
    const int c = threadIdx.x;
    float acc = br[c];
    #pragma unroll 16
    for (int l = 0; l < Ll; l++)
        acc += bl[h * Ll + l] * Wr[l * DKk + c];
    beff[h * DKk + c] = acc;
}

// ---------------------------------------------------------------------------
// 32x32 tiled transpose + tf32 round + k-perm on output columns
// ---------------------------------------------------------------------------
__global__ __launch_bounds__(256) void transpose_kernel(
    const float* __restrict__ in, float* __restrict__ out)
{
    __shared__ float tile[32][33];
    const int bx = blockIdx.x * 32;
    const int by = blockIdx.y * 32;
    const int tx = threadIdx.x & 31;
    const int ty = threadIdx.x >> 5;
    #pragma unroll
    for (int i = 0; i < 32; i += 8)
        tile[ty + i][tx] = in[(size_t)(by + ty + i) * Dmod + bx + tx];
    __syncthreads();
    const int ktx = perm8(tx);
    #pragma unroll
    for (int i = 0; i < 32; i += 8)
        out[(size_t)(bx + ty + i) * Dmod + by + ktx] =
            __uint_as_float(f2tf32(tile[tx][ty + i]));
}

// ---------------------------------------------------------------------------
// Tensor-core tf32 GEMM:  C[M,N] = A[M,K] @ WT[N,K]^T + bias[N]
// A and WT are pre-rounded to tf32 and k-permuted -> no CVT, LDS.64 fragments.
// CTA 128x128, BK=32, 2-stage cp.async pipeline, 256 threads, smem stride 40.
// ---------------------------------------------------------------------------
#define G_BK 32
#define G_NK (Dmod / G_BK)
#define G_STRIDE 40
#define G_OP_FLOATS (128 * G_STRIDE)
#define G_STAGE_FLOATS (2 * G_OP_FLOATS)
#define G_SMEM_BYTES (2 * G_STAGE_FLOATS * 4)   // 81920 B

template<bool TRANS_OUT>
__global__ __launch_bounds__(256, 2) void gemm_tc_kernel(
    const float* __restrict__ A, const float* __restrict__ WT,
    const float* __restrict__ bias, float* __restrict__ C)
{
    extern __shared__ float smf[];
    const uint32_t smem_base = smem_u32(smf);

    const int t    = threadIdx.x;
    const int wid  = t >> 5;
    const int lane = t & 31;
    const int g    = lane >> 2;
    const int tid4 = lane & 3;
    const int wm   = wid >> 2;
    const int wn   = wid & 3;
    const int m0 = blockIdx.y * 128;
    const int n0 = blockIdx.x * 128;

    float acc[4][4][4];
    #pragma unroll
    for (int mf = 0; mf < 4; mf++)
        #pragma unroll
        for (int nf = 0; nf < 4; nf++)
            #pragma unroll
            for (int r = 0; r < 4; r++) acc[mf][nf][r] = 0.f;

    auto load_stage = [&](int s, int k0) {
        const uint32_t aB = smem_base + (uint32_t)s * G_STAGE_FLOATS * 4;
        const uint32_t bB = aB + G_OP_FLOATS * 4;
        #pragma unroll
        for (int i = 0; i < 4; i++) {
            int u = t + i * 256;
            int row = u >> 3, c4 = u & 7;
            uint32_t off = (uint32_t)(row * G_STRIDE + c4 * 4) * 4;
            CP_ASYNC16(aB + off, A + (size_t)(m0 + row) * Dmod + k0 + c4 * 4);
        }
        #pragma unroll
        for (int i = 0; i < 4; i++) {
            int u = t + i * 256;
            int row = u >> 3, c4 = u & 7;
            uint32_t off = (uint32_t)(row * G_STRIDE + c4 * 4) * 4;
            CP_ASYNC16(bB + off, WT + (size_t)(n0 + row) * Dmod + k0 + c4 * 4);
        }
    };

    load_stage(0, 0);
    CP_COMMIT();
    load_stage(1, G_BK);
    CP_COMMIT();

    for (int k = 0; k < G_NK; k++) {
        const int s = k & 1;
        CP_WAIT(1);
        __syncthreads();

        const uint32_t* sA = (const uint32_t*)(smf + (size_t)s * G_STAGE_FLOATS);
        const uint32_t* sB = sA + G_OP_FLOATS;

        #pragma unroll
        for (int ks = 0; ks < 4; ks++) {
            const int kc2 = ks * 8 + 2 * tid4;   // permuted pair position
            uint32_t af[4][4], bf[4][2];
            #pragma unroll
            for (int mf = 0; mf < 4; mf++) {
                const int r0 = wm * 64 + mf * 16;
                uint2 u0 = *(const uint2*)&sA[(r0 + g) * G_STRIDE + kc2];
                uint2 u1 = *(const uint2*)&sA[(r0 + g + 8) * G_STRIDE + kc2];
                af[mf][0] = u0.x; af[mf][2] = u0.y;
                af[mf][1] = u1.x; af[mf][3] = u1.y;
            }
            #pragma unroll
            for (int nf = 0; nf < 4; nf++) {
                const int c0 = wn * 32 + nf * 8;
                uint2 ub = *(const uint2*)&sB[(c0 + g) * G_STRIDE + kc2];
                bf[nf][0] = ub.x; bf[nf][1] = ub.y;
            }
            #pragma unroll
            for (int mf = 0; mf < 4; mf++)
                #pragma unroll
                for (int nf = 0; nf < 4; nf++)
                    mma_tf32(acc[mf][nf], af[mf], bf[nf]);
        }

        __syncthreads();
        if (k + 2 < G_NK) load_stage(s, (k + 2) * G_BK);
        CP_COMMIT();
    }

    #pragma unroll
    for (int mf = 0; mf < 4; mf++) {
        const int r0 = m0 + wm * 64 + mf * 16 + g;
        #pragma unroll
        for (int nf = 0; nf < 4; nf++) {
            const int c0 = n0 + wn * 32 + nf * 8 + 2 * tid4;
            const float b0 = bias[c0], b1 = bias[c0 + 1];
            if (!TRANS_OUT) {
                float2 v0 = make_float2(acc[mf][nf][0] + b0, acc[mf][nf][1] + b1);
                float2 v1 = make_float2(acc[mf][nf][2] + b0, acc[mf][nf][3] + b1);
                *(float2*)(C + (size_t)r0 * Dmod + c0)       = v0;
                *(float2*)(C + (size_t)(r0 + 8) * Dmod + c0) = v1;
            } else {
                const int bb = r0 >> 11, s0 = r0 & 2047;
                const int hh = c0 >> 7,  dd = c0 & 127;
                float* base = C + ((size_t)(bb * Hh + hh) * DKk + dd) * Sseq;
                base[s0]            = acc[mf][nf][0] + b0;
                base[Sseq + s0]     = acc[mf][nf][1] + b1;
                base[s0 + 8]        = acc[mf][nf][2] + b0;
                base[Sseq + s0 + 8] = acc[mf][nf][3] + b1;
            }
        }
    }
}

// ---------------------------------------------------------------------------
// Tensor-core causal flash attention, bf16 hi/lo split (x3 MMA).
// K/V smem planes stored k-pair-permuted -> LDS.64 fragment reads.
// KROWW=72, VROWW=40 (≡8 mod 32 -> conflict-free 64-bit reads).
// ---------------------------------------------------------------------------
#define KROWW 72
#define VROWW 40
#define FA_SMEM_WORDS (2 * 64 * KROWW + 2 * 128 * VROWW)   // 19456
#define FA_SMEM_BYTES (FA_SMEM_WORDS * 4)                  // 77824 B

__global__ __launch_bounds__(256, 1) void fa_tc_kernel(
    const float* __restrict__ Q, const float* __restrict__ K,
    const float* __restrict__ VT, float* __restrict__ O)
{
    extern __shared__ uint32_t su[];
    uint32_t* Khi = su;
    uint32_t* Klo = su + 64 * KROWW;
    uint32_t* Vhi = su + 2 * 64 * KROWW;
    uint32_t* Vlo = Vhi + 128 * VROWW;

    const int qb = (int)gridDim.x - 1 - (int)blockIdx.x;
    const int h  = blockIdx.y;
    const int b  = blockIdx.z;
    const int t  = threadIdx.x;
    const int w  = t >> 5;
    const int lane = t & 31;
    const int g  = lane >> 2;
    const int t4 = lane & 3;
    const int q0 = qb * 128;

    const size_t bh_off = (size_t)b * Sseq * Dmod + (size_t)h * DKk;
    const float* Kg  = K + bh_off;
    const float* VTg = VT + (size_t)(b * Hh + h) * DKk * Sseq;

    const float qscale = 0.088388347648318447f * 1.4426950408889634f;
    uint32_t qhi[8][4], qlo[8][4];
    {
        const float* Qw = Q + bh_off + (size_t)(q0 + w * 16) * Dmod;
        #pragma unroll
        for (int ks = 0; ks < 8; ks++) {
            const int d0 = ks * 16 + 2 * t4;
            float2 x0 = *(const float2*)(Qw + (size_t)g * Dmod + d0);
            float2 x1 = *(const float2*)(Qw + (size_t)(g + 8) * Dmod + d0);
            float2 x2 = *(const float2*)(Qw + (size_t)g * Dmod + d0 + 8);
            float2 x3 = *(const float2*)(Qw + (size_t)(g + 8) * Dmod + d0 + 8);
            split2(x0.x * qscale, x0.y * qscale, qhi[ks][0], qlo[ks][0]);
            split2(x1.x * qscale, x1.y * qscale, qhi[ks][1], qlo[ks][1]);
            split2(x2.x * qscale, x2.y * qscale, qhi[ks][2], qlo[ks][2]);
            split2(x3.x * qscale, x3.y * qscale, qhi[ks][3], qlo[ks][3]);
        }
    }

    float oacc[16][4];
    #pragma unroll
    for (int nf = 0; nf < 16; nf++)
        #pragma unroll
        for (int r = 0; r < 4; r++) oacc[nf][r] = 0.f;

    float m0 = -1e30f, m1 = -1e30f, l0 = 0.f, l1 = 0.f;
    const int row0 = q0 + w * 16 + g;
    const int row1 = row0 + 8;

    const int ntiles = 2 * qb + 2;
    for (int kt = 0; kt < ntiles; kt++) {
        const int kv0 = kt * 64;

        // ---- load K tile [64 kv][128 d] -> hi/lo planes, permuted words ----
        #pragma unroll
        for (int i = 0; i < 8; i++) {
            int u = t + i * 256;
            int c4 = u & 31, kv = u >> 5;
            float4 x = *(const float4*)(Kg + (size_t)(kv0 + kv) * Dmod + 4 * c4);
            uint32_t h0, e0, h1, e1;
            split2(x.x, x.y, h0, e0);
            split2(x.z, x.w, h1, e1);
            const int p0 = perm8(2 * c4), p1 = perm8(2 * c4 + 1);
            Khi[kv * KROWW + p0] = h0;
            Khi[kv * KROWW + p1] = h1;
            Klo[kv * KROWW + p0] = e0;
            Klo[kv * KROWW + p1] = e1;
        }
        // ---- load V tile [128 d][64 kv] from VT, permuted words ----
        #pragma unroll
        for (int i = 0; i < 8; i++) {
            int u = t + i * 256;
            int c4 = u & 15, d = u >> 4;
            float4 x = *(const float4*)(VTg + (size_t)d * Sseq + kv0 + 4 * c4);
            uint32_t h0, e0, h1, e1;
            split2(x.x, x.y, h0, e0);
            split2(x.z, x.w, h1, e1);
            const int p0 = perm8(2 * c4), p1 = perm8(2 * c4 + 1);
            Vhi[d * VROWW + p0] = h0;
            Vhi[d * VROWW + p1] = h1;
            Vlo[d * VROWW + p0] = e0;
            Vlo[d * VROWW + p1] = e1;
        }
        __syncthreads();

        // ---- QK^T ----
        float acc[8][4];
        #pragma unroll
        for (int nf = 0; nf < 8; nf++)
            #pragma unroll
            for (int r = 0; r < 4; r++) acc[nf][r] = 0.f;

        #pragma unroll
        for (int ks = 0; ks < 8; ks++) {
            #pragma unroll
            for (int nf = 0; nf < 8; nf++) {
                const int r = (nf * 8 + g) * KROWW + 8 * ks + 2 * t4;
                uint2 bh = *(const uint2*)&Khi[r];
                uint2 bl = *(const uint2*)&Klo[r];
                mma_bf16(acc[nf], qhi[ks], bh.x, bh.y);
                mma_bf16(acc[nf], qhi[ks], bl.x, bl.y);
                mma_bf16(acc[nf], qlo[ks], bh.x, bh.y);
            }
        }

        // ---- causal mask ----
        if (kv0 + 63 > q0) {
            #pragma unroll
            for (int nf = 0; nf < 8; nf++) {
                const int c = kv0 + nf * 8 + 2 * t4;
                if (c     > row0) acc[nf][0] = -1e30f;
                if (c + 1 > row0) acc[nf][1] = -1e30f;
                if (c     > row1) acc[nf][2] = -1e30f;
                if (c + 1 > row1) acc[nf][3] = -1e30f;
            }
        }

        // ---- online softmax ----
        float mx0 = -1e30f, mx1 = -1e30f;
        #pragma unroll
        for (int nf = 0; nf < 8; nf++) {
            mx0 = fmaxf(mx0, fmaxf(acc[nf][0], acc[nf][1]));
            mx1 = fmaxf(mx1, fmaxf(acc[nf][2], acc[nf][3]));
        }
        mx0 = fmaxf(mx0, __shfl_xor_sync(0xFFFFFFFFu, mx0, 1));
        mx0 = fmaxf(mx0, __shfl_xor_sync(0xFFFFFFFFu, mx0, 2));
        mx1 = fmaxf(mx1, __shfl_xor_sync(0xFFFFFFFFu, mx1, 1));
        mx1 = fmaxf(mx1, __shfl_xor_sync(0xFFFFFFFFu, mx1, 2));

        const float mn0 = fmaxf(m0, mx0);
        const float mn1 = fmaxf(m1, mx1);
        const float cr0 = ex2(m0 - mn0);
        const float cr1 = ex2(m1 - mn1);

        float ps0 = 0.f, ps1 = 0.f;
        #pragma unroll
        for (int nf = 0; nf < 8; nf++) {
            acc[nf][0] = ex2(acc[nf][0] - mn0);
            acc[nf][1] = ex2(acc[nf][1] - mn0);
            acc[nf][2] = ex2(acc[nf][2] - mn1);
            acc[nf][3] = ex2(acc[nf][3] - mn1);
            ps0 += acc[nf][0] + acc[nf][1];
            ps1 += acc[nf][2] + acc[nf][3];
        }
        ps0 += __shfl_xor_sync(0xFFFFFFFFu, ps0, 1);
        ps0 += __shfl_xor_sync(0xFFFFFFFFu, ps0, 2);
        ps1 += __shfl_xor_sync(0xFFFFFFFFu, ps1, 1);
        ps1 += __shfl_xor_sync(0xFFFFFFFFu, ps1, 2);

        l0 = l0 * cr0 + ps0;
        l1 = l1 * cr1 + ps1;
        m0 = mn0;
        m1 = mn1;

        #pragma unroll
        for (int nf = 0; nf < 16; nf++) {
            oacc[nf][0] *= cr0;
            oacc[nf][1] *= cr0;
            oacc[nf][2] *= cr1;
            oacc[nf][3] *= cr1;
        }

        // ---- P @ V ----
        #pragma unroll
        for (int ks2 = 0; ks2 < 4; ks2++) {
            uint32_t ahi[4], alo[4];
            split2(acc[2 * ks2][0],     acc[2 * ks2][1],     ahi[0], alo[0]);
            split2(acc[2 * ks2][2],     acc[2 * ks2][3],     ahi[1], alo[1]);
            split2(acc[2 * ks2 + 1][0], acc[2 * ks2 + 1][1], ahi[2], alo[2]);
            split2(acc[2 * ks2 + 1][2], acc[2 * ks2 + 1][3], ahi[3], alo[3]);
            #pragma unroll
            for (int nf = 0; nf < 16; nf++) {
                const int r = (nf * 8 + g) * VROWW + 8 * ks2 + 2 * t4;
                uint2 bh = *(const uint2*)&Vhi[r];
                uint2 bl = *(const uint2*)&Vlo[r];
                mma_bf16(oacc[nf], ahi, bh.x, bh.y);
                mma_bf16(oacc[nf], ahi, bl.x, bl.y);
                mma_bf16(oacc[nf], alo, bh.x, bh.y);
            }
        }
        __syncthreads();
    }

    // ---- epilogue ----
    const float inv0 = 1.0f / l0;
    const float inv1 = 1.0f / l1;
    float* Ow = O + bh_off + (size_t)(q0 + w * 16) * Dmod;
    #pragma unroll
    for (int nf = 0; nf < 16; nf++) {
        const int col = nf * 8 + 2 * t4;
        *(float2*)(Ow + (size_t)g * Dmod + col) =
            make_float2(oacc[nf][0] * inv0, oacc[nf][1] * inv0);
        *(float2*)(Ow + (size_t)(g + 8) * Dmod + col) =
            make_float2(oacc[nf][2] * inv1, oacc[nf][3] * inv1);
    }
}

// ---------------------------------------------------------------------------
// kernel_launch
// ---------------------------------------------------------------------------
extern "C" void kernel_launch(void* const* d_in, const int* in_sizes, int n_in,
                              void* d_out, int out_size)
{
    const float* queries = (const float*)d_in[0];
    const float* keys    = (const float*)d_in[1];
    const float* values  = (const float*)d_in[2];
    const float* Wq      = (const float*)d_in[3];
    const float* bq      = (const float*)d_in[4];
    const float* Wlk     = (const float*)d_in[5];
    const float* blk     = (const float*)d_in[6];
    const float* Wlv     = (const float*)d_in[7];
    const float* blv     = (const float*)d_in[8];
    const float* Wkr     = (const float*)d_in[9];
    const float* bkr     = (const float*)d_in[10];
    const float* Wvr     = (const float*)d_in[11];
    const float* bvr     = (const float*)d_in[12];
    const float* Wo      = (const float*)d_in[13];
    const float* bo      = (const float*)d_in[14];
    float* out = (float*)d_out;

    float *Q, *K, *VT, *O, *Ar, *Wtmp, *WqT, *WkT, *WvT, *WoT, *bk, *bv;
    cudaGetSymbolAddress((void**)&Q,    g_Q);
    cudaGetSymbolAddress((void**)&K,    g_K);
    cudaGetSymbolAddress((void**)&VT,   g_VT);
    cudaGetSymbolAddress((void**)&O,    g_O);
    cudaGetSymbolAddress((void**)&Ar,   g_Ar);
    cudaGetSymbolAddress((void**)&Wtmp, g_Wtmp);
    cudaGetSymbolAddress((void**)&WqT,  g_WqT);
    cudaGetSymbolAddress((void**)&WkT,  g_WkT);
    cudaGetSymbolAddress((void**)&WvT,  g_WvT);
    cudaGetSymbolAddress((void**)&WoT,  g_WoT);
    cudaGetSymbolAddress((void**)&bk,   g_bk);
    cudaGetSymbolAddress((void**)&bv,   g_bv);

    cudaFuncSetAttribute(gemm_tc_kernel<false>,
                         cudaFuncAttributeMaxDynamicSharedMemorySize, G_SMEM_BYTES);
    cudaFuncSetAttribute(gemm_tc_kernel<true>,
                         cudaFuncAttributeMaxDynamicSharedMemorySize, G_SMEM_BYTES);
    cudaFuncSetAttribute(fa_tc_kernel,
                         cudaFuncAttributeMaxDynamicSharedMemorySize, FA_SMEM_BYTES);

    const dim3 tgrid(Dmod / 32, Dmod / 32);
    const dim3 ggrid(Dmod / 128, Mrows / 128);
    const int rblocks = (int)(((size_t)Mrows * Dmod / 4) / 256);

    // Q projection
    transpose_kernel<<<tgrid, 256>>>(Wq, WqT);
    round_perm_kernel<<<rblocks, 256>>>(queries, Ar);
    gemm_tc_kernel<false><<<ggrid, 256, G_SMEM_BYTES>>>(Ar, WqT, bq, Q);

    // K projection
    fold_w_kernel<<<dim3(Dmod, Hh), 128>>>(Wlk, Wkr, Wtmp);
    fold_b_kernel<<<Hh, 128>>>(blk, Wkr, bkr, bk);
    transpose_kernel<<<tgrid, 256>>>(Wtmp, WkT);
    round_perm_kernel<<<rblocks, 256>>>(keys, Ar);
    gemm_tc_kernel<false><<<ggrid, 256, G_SMEM_BYTES>>>(Ar, WkT, bk, K);

    // V projection (transposed output)
    fold_w_kernel<<<dim3(Dmod, Hh), 128>>>(Wlv, Wvr, Wtmp);
    fold_b_kernel<<<Hh, 128>>>(blv, Wvr, bvr, bv);
    transpose_kernel<<<tgrid, 256>>>(Wtmp, WvT);
    round_perm_kernel<<<rblocks, 256>>>(values, Ar);
    gemm_tc_kernel<true><<<ggrid, 256, G_SMEM_BYTES>>>(Ar, WvT, bv, VT);

    // Fused causal attention
    fa_tc_kernel<<<dim3(Sseq / 128, Hh, Bsz), 256, FA_SMEM_BYTES>>>(Q, K, VT, O);

    // Output projection
    transpose_kernel<<<tgrid, 256>>>(Wo, WoT);
    round_perm_kernel<<<rblocks, 256>>>(O, Ar);
    gemm_tc_kernel<false><<<ggrid, 256, G_SMEM_BYTES>>>(Ar, WoT, bo, out);
}

// round 6
// speedup vs baseline: 4.3529x; 1.1059x over previous
#include <cuda_runtime.h>
#include <cuda_bf16.h>
#include <math.h>
#include <cstdint>

// Problem constants
#define Bsz   2
#define Sseq  2048
#define Dmod  2048
#define Hh    16
#define DKk   128
#define Ll    64
#define Mrows (Bsz * Sseq)   // 4096

// ---------------------------------------------------------------------------
// Device scratch
// ---------------------------------------------------------------------------
__device__ float    g_Q  [(size_t)Mrows * Dmod];
__device__ float    g_Ar [(size_t)Mrows * Dmod];
__device__ uint32_t g_Khi[(size_t)Mrows * 1024];  // [b,h,s][64 words]
__device__ uint32_t g_Klo[(size_t)Mrows * 1024];
__device__ uint32_t g_Vhi[(size_t)Mrows * 1024];  // [b,h,d][1024 words]
__device__ uint32_t g_Vlo[(size_t)Mrows * 1024];
__device__ float    g_WqT[(size_t)Dmod * Dmod];
__device__ float    g_WkT[(size_t)Dmod * Dmod];
__device__ float    g_WvT[(size_t)Dmod * Dmod];
__device__ float    g_WoT[(size_t)Dmod * Dmod];
__device__ float    g_bk[Dmod];
__device__ float    g_bv[Dmod];

// ---------------------------------------------------------------------------
// Helpers
// ---------------------------------------------------------------------------
__device__ __forceinline__ uint32_t smem_u32(const void* p) {
    uint32_t a;
    asm("{ .reg .u64 t; cvta.to.shared.u64 t, %1; cvt.u32.u64 %0, t; }"
        : "=r"(a) : "l"(p));
    return a;
}

#define CP_ASYNC16(dst, src) \
    asm volatile("cp.async.cg.shared.global [%0], [%1], 16;" \
        :: "r"((uint32_t)(dst)), "l"(src) : "memory")
#define CP_COMMIT() asm volatile("cp.async.commit_group;" ::: "memory")
#define CP_WAIT(n)  asm volatile("cp.async.wait_group %0;" :: "n"(n) : "memory")

__device__ __forceinline__ uint32_t f2tf32(float x) {
    uint32_t r;
    asm("cvt.rna.tf32.f32 %0, %1;" : "=r"(r) : "f"(x));
    return r;
}

__device__ __forceinline__ void mma_tf32(float* c, const uint32_t* a, const uint32_t* b) {
    asm volatile(
        "mma.sync.aligned.m16n8k8.row.col.f32.tf32.tf32.f32 "
        "{%0,%1,%2,%3}, {%4,%5,%6,%7}, {%8,%9}, {%0,%1,%2,%3};"
        : "+f"(c[0]), "+f"(c[1]), "+f"(c[2]), "+f"(c[3])
        : "r"(a[0]), "r"(a[1]), "r"(a[2]), "r"(a[3]), "r"(b[0]), "r"(b[1]));
}

__device__ __forceinline__ void mma_bf16(float* c, const uint32_t* a,
                                         uint32_t b0, uint32_t b1) {
    asm volatile(
        "mma.sync.aligned.m16n8k16.row.col.f32.bf16.bf16.f32 "
        "{%0,%1,%2,%3}, {%4,%5,%6,%7}, {%8,%9}, {%0,%1,%2,%3};"
        : "+f"(c[0]), "+f"(c[1]), "+f"(c[2]), "+f"(c[3])
        : "r"(a[0]), "r"(a[1]), "r"(a[2]), "r"(a[3]), "r"(b0), "r"(b1));
}

__device__ __forceinline__ uint32_t packbf(float e0, float e1) {
    uint32_t r;
    asm("cvt.rn.bf16x2.f32 %0, %1, %2;" : "=r"(r) : "f"(e1), "f"(e0));
    return r;
}

__device__ __forceinline__ void split2(float e0, float e1,
                                       uint32_t& hi, uint32_t& lo) {
    hi = packbf(e0, e1);
    float r0 = e0 - __uint_as_float(hi << 16);
    float r1 = e1 - __uint_as_float(hi & 0xFFFF0000u);
    lo = packbf(r0, r1);
}

__device__ __forceinline__ float ex2(float x) {
    float y;
    asm("ex2.approx.ftz.f32 %0, %1;" : "=f"(y) : "f"(x));
    return y;
}

// ---------------------------------------------------------------------------
// Round activations to tf32 + k-perm, fully coalesced (8 elems / thread).
// group perm: stored[q] <- v[r], perm(r)=q; q order = v0 v4 v1 v5 v2 v6 v3 v7
// ---------------------------------------------------------------------------
__global__ __launch_bounds__(256) void round_perm_kernel(
    const float* __restrict__ in, float* __restrict__ out)
{
    const size_t base = ((size_t)blockIdx.x * 256 + threadIdx.x) * 8;
    const float4 a = *(const float4*)(in + base);
    const float4 b = *(const float4*)(in + base + 4);
    float4 oa, ob;
    oa.x = __uint_as_float(f2tf32(a.x));
    oa.y = __uint_as_float(f2tf32(b.x));
    oa.z = __uint_as_float(f2tf32(a.y));
    oa.w = __uint_as_float(f2tf32(b.y));
    ob.x = __uint_as_float(f2tf32(a.z));
    ob.y = __uint_as_float(f2tf32(b.z));
    ob.z = __uint_as_float(f2tf32(a.w));
    ob.w = __uint_as_float(f2tf32(b.w));
    *(float4*)(out + base)     = oa;
    *(float4*)(out + base + 4) = ob;
}

// ---------------------------------------------------------------------------
// Fused fold + transpose: WT[h*128+c][d] = sum_l Wl[d][h*64+l] * Wr[l][c],
// rounded to tf32 and k-permuted along d. Grid (16 dblk, 16 h), 256 thr.
// ---------------------------------------------------------------------------
#define FT_SMEM_BYTES ((64 * 132 + 64 * 128) * 4)   // 66560

__global__ __launch_bounds__(256) void foldT_kernel(
    const float* __restrict__ Wl, const float* __restrict__ Wr,
    float* __restrict__ WT)
{
    extern __shared__ float fsm[];
    float* sWl = fsm;             // [l][132] (d-indexed rows, padded)
    float* sWr = fsm + 64 * 132;  // [l][128]

    const int dblk = blockIdx.x;
    const int h    = blockIdx.y;
    const int t    = threadIdx.x;

    #pragma unroll
    for (int i = 0; i < 8; i++) {
        int u = t + i * 256;          // 2048 float4 units
        int l = u >> 5, c4 = u & 31;
        *(float4*)&sWr[l * 128 + c4 * 4] = *(const float4*)(Wr + l * DKk + c4 * 4);
    }
    #pragma unroll
    for (int i = 0; i < 8; i++) {
        int u = t + i * 256;          // 2048 float4 units
        int d = u >> 4, l4 = u & 15;
        float4 x = *(const float4*)(Wl + (size_t)(dblk * 128 + d) * (Hh * Ll)
                                    + h * Ll + l4 * 4);
        sWl[(l4 * 4 + 0) * 132 + d] = x.x;
        sWl[(l4 * 4 + 1) * 132 + d] = x.y;
        sWl[(l4 * 4 + 2) * 132 + d] = x.z;
        sWl[(l4 * 4 + 3) * 132 + d] = x.w;
    }
    __syncthreads();

    const int d8 = (t & 15) * 8;   // 8 d-values per thread
    const int cg = t >> 4;         // 16 c-values per thread group
    float acc[8][8];
    #pragma unroll
    for (int dd = 0; dd < 8; dd++)
        #pragma unroll
        for (int j = 0; j < 8; j++) acc[dd][j] = 0.f;

    for (int l = 0; l < Ll; l++) {
        float4 a0 = *(float4*)&sWl[l * 132 + d8];
        float4 a1 = *(float4*)&sWl[l * 132 + d8 + 4];
        const float* wr = &sWr[l * 128 + cg * 8];
        #pragma unroll
        for (int j = 0; j < 8; j++) {
            float wv = wr[j];
            acc[0][j] += a0.x * wv;
            acc[1][j] += a0.y * wv;
            acc[2][j] += a0.z * wv;
            acc[3][j] += a0.w * wv;
            acc[4][j] += a1.x * wv;
            acc[5][j] += a1.y * wv;
            acc[6][j] += a1.z * wv;
            acc[7][j] += a1.w * wv;
        }
    }

    #pragma unroll
    for (int j = 0; j < 8; j++) {
        const int n = h * 128 + cg * 8 + j;
        float* dst = WT + (size_t)n * Dmod + dblk * 128 + d8;
        float4 oa, ob;
        oa.x = __uint_as_float(f2tf32(acc[0][j]));
        oa.y = __uint_as_float(f2tf32(acc[4][j]));
        oa.z = __uint_as_float(f2tf32(acc[1][j]));
        oa.w = __uint_as_float(f2tf32(acc[5][j]));
        ob.x = __uint_as_float(f2tf32(acc[2][j]));
        ob.y = __uint_as_float(f2tf32(acc[6][j]));
        ob.z = __uint_as_float(f2tf32(acc[3][j]));
        ob.w = __uint_as_float(f2tf32(acc[7][j]));
        *(float4*)dst       = oa;
        *(float4*)(dst + 4) = ob;
    }
}

__global__ __launch_bounds__(128) void fold_b_kernel(
    const float* __restrict__ bl, const float* __restrict__ Wr,
    const float* __restrict__ br, float* __restrict__ beff)
{
    const int h = blockIdx.x;
    const int c = threadIdx.x;
    float acc = br[c];
    #pragma unroll 16
    for (int l = 0; l < Ll; l++)
        acc += bl[h * Ll + l] * Wr[l * DKk + c];
    beff[h * DKk + c] = acc;
}

// ---------------------------------------------------------------------------
// 32x32 tiled transpose + tf32 round + k-perm (for Wq, Wo)
// ---------------------------------------------------------------------------
__device__ __forceinline__ int perm8i(int w) {
    return (w & ~7) | (((w & 3) << 1) | ((w >> 2) & 1));
}

__global__ __launch_bounds__(256) void transpose_kernel(
    const float* __restrict__ in, float* __restrict__ out)
{
    __shared__ float tile[32][33];
    const int bx = blockIdx.x * 32;
    const int by = blockIdx.y * 32;
    const int tx = threadIdx.x & 31;
    const int ty = threadIdx.x >> 5;
    #pragma unroll
    for (int i = 0; i < 32; i += 8)
        tile[ty + i][tx] = in[(size_t)(by + ty + i) * Dmod + bx + tx];
    __syncthreads();
    const int ktx = perm8i(tx);
    #pragma unroll
    for (int i = 0; i < 32; i += 8)
        out[(size_t)(bx + ty + i) * Dmod + by + ktx] =
            __uint_as_float(f2tf32(tile[tx][ty + i]));
}

// ---------------------------------------------------------------------------
// Tensor-core tf32 GEMM:  C = A @ WT^T + bias.  A/WT pre-rounded+permuted.
// MODE 0: fp32 row-major out. MODE 1: K bf16 hi/lo split planes [bh,s,words].
// MODE 2: V bf16 hi/lo split planes, transposed [bh,d,s-words].
// ---------------------------------------------------------------------------
#define G_BK 32
#define G_NK (Dmod / G_BK)
#define G_STRIDE 40
#define G_OP_FLOATS (128 * G_STRIDE)
#define G_STAGE_FLOATS (2 * G_OP_FLOATS)
#define G_SMEM_BYTES (2 * G_STAGE_FLOATS * 4)

template<int MODE>
__global__ __launch_bounds__(256, 2) void gemm_tc_kernel(
    const float* __restrict__ A, const float* __restrict__ WT,
    const float* __restrict__ bias, float* __restrict__ C,
    uint32_t* __restrict__ Chi, uint32_t* __restrict__ Clo)
{
    extern __shared__ float smf[];
    const uint32_t smem_base = smem_u32(smf);

    const int t    = threadIdx.x;
    const int wid  = t >> 5;
    const int lane = t & 31;
    const int g    = lane >> 2;
    const int tid4 = lane & 3;
    const int wm   = wid >> 2;
    const int wn   = wid & 3;
    const int m0 = blockIdx.y * 128;
    const int n0 = blockIdx.x * 128;

    float acc[4][4][4];
    #pragma unroll
    for (int mf = 0; mf < 4; mf++)
        #pragma unroll
        for (int nf = 0; nf < 4; nf++)
            #pragma unroll
            for (int r = 0; r < 4; r++) acc[mf][nf][r] = 0.f;

    auto load_stage = [&](int s, int k0) {
        const uint32_t aB = smem_base + (uint32_t)s * G_STAGE_FLOATS * 4;
        const uint32_t bB = aB + G_OP_FLOATS * 4;
        #pragma unroll
        for (int i = 0; i < 4; i++) {
            int u = t + i * 256;
            int row = u >> 3, c4 = u & 7;
            uint32_t off = (uint32_t)(row * G_STRIDE + c4 * 4) * 4;
            CP_ASYNC16(aB + off, A + (size_t)(m0 + row) * Dmod + k0 + c4 * 4);
        }
        #pragma unroll
        for (int i = 0; i < 4; i++) {
            int u = t + i * 256;
            int row = u >> 3, c4 = u & 7;
            uint32_t off = (uint32_t)(row * G_STRIDE + c4 * 4) * 4;
            CP_ASYNC16(bB + off, WT + (size_t)(n0 + row) * Dmod + k0 + c4 * 4);
        }
    };

    load_stage(0, 0);
    CP_COMMIT();
    load_stage(1, G_BK);
    CP_COMMIT();

    for (int k = 0; k < G_NK; k++) {
        const int s = k & 1;
        CP_WAIT(1);
        __syncthreads();

        const uint32_t* sA = (const uint32_t*)(smf + (size_t)s * G_STAGE_FLOATS);
        const uint32_t* sB = sA + G_OP_FLOATS;

        #pragma unroll
        for (int ks = 0; ks < 4; ks++) {
            const int kc2 = ks * 8 + 2 * tid4;
            uint32_t af[4][4], bf[4][2];
            #pragma unroll
            for (int mf = 0; mf < 4; mf++) {
                const int r0 = wm * 64 + mf * 16;
                uint2 u0 = *(const uint2*)&sA[(r0 + g) * G_STRIDE + kc2];
                uint2 u1 = *(const uint2*)&sA[(r0 + g + 8) * G_STRIDE + kc2];
                af[mf][0] = u0.x; af[mf][2] = u0.y;
                af[mf][1] = u1.x; af[mf][3] = u1.y;
            }
            #pragma unroll
            for (int nf = 0; nf < 4; nf++) {
                const int c0 = wn * 32 + nf * 8;
                uint2 ub = *(const uint2*)&sB[(c0 + g) * G_STRIDE + kc2];
                bf[nf][0] = ub.x; bf[nf][1] = ub.y;
            }
            #pragma unroll
            for (int mf = 0; mf < 4; mf++)
                #pragma unroll
                for (int nf = 0; nf < 4; nf++)
                    mma_tf32(acc[mf][nf], af[mf], bf[nf]);
        }

        __syncthreads();
        if (k + 2 < G_NK) load_stage(s, (k + 2) * G_BK);
        CP_COMMIT();
    }

    #pragma unroll
    for (int mf = 0; mf < 4; mf++) {
        const int r0 = m0 + wm * 64 + mf * 16 + g;
        #pragma unroll
        for (int nf = 0; nf < 4; nf++) {
            const int c0 = n0 + wn * 32 + nf * 8 + 2 * tid4;
            const float b0 = bias[c0], b1 = bias[c0 + 1];
            float v0 = acc[mf][nf][0] + b0, v1 = acc[mf][nf][1] + b1;
            float v2 = acc[mf][nf][2] + b0, v3 = acc[mf][nf][3] + b1;
            if (MODE == 0) {
                *(float2*)(C + (size_t)r0 * Dmod + c0)       = make_float2(v0, v1);
                *(float2*)(C + (size_t)(r0 + 8) * Dmod + c0) = make_float2(v2, v3);
            } else if (MODE == 1) {
                const int bb = r0 >> 11, s = r0 & 2047, hh = c0 >> 7;
                const int j = (c0 & 127) >> 1;
                const int p = (j & ~7) | (2 * tid4 + (nf & 1));
                const size_t base = ((size_t)(bb * Hh + hh) * Sseq + s) * 64 + p;
                uint32_t hi, lo;
                split2(v0, v1, hi, lo);
                Chi[base] = hi; Clo[base] = lo;
                split2(v2, v3, hi, lo);
                Chi[base + 512] = hi; Clo[base + 512] = lo;
            } else {
                float u0 = __shfl_xor_sync(0xFFFFFFFFu, v0, 4);
                float u1 = __shfl_xor_sync(0xFFFFFFFFu, v1, 4);
                float u2 = __shfl_xor_sync(0xFFFFFFFFu, v2, 4);
                float u3 = __shfl_xor_sync(0xFFFFFFFFu, v3, 4);
                if ((g & 1) == 0) {
                    const int bb = r0 >> 11, s = r0 & 2047, hh = c0 >> 7;
                    const int d = c0 & 127;
                    const size_t base0 =
                        ((size_t)(bb * Hh + hh) * DKk + d) * 1024 + ((s & ~15) >> 1);
                    uint32_t hi, lo;
                    split2(v0, u0, hi, lo);
                    Chi[base0 + g] = hi;            Clo[base0 + g] = lo;
                    split2(v2, u2, hi, lo);
                    Chi[base0 + g + 1] = hi;        Clo[base0 + g + 1] = lo;
                    split2(v1, u1, hi, lo);
                    Chi[base0 + 1024 + g] = hi;     Clo[base0 + 1024 + g] = lo;
                    split2(v3, u3, hi, lo);
                    Chi[base0 + 1024 + g + 1] = hi; Clo[base0 + 1024 + g + 1] = lo;
                }
            }
        }
    }
}

// ---------------------------------------------------------------------------
// Tensor-core causal FA: K/V pre-split bf16 planes, cp.async double-buffered.
// Epilogue writes tf32-rounded, k-permuted output into Ar.
// ---------------------------------------------------------------------------
#define KROWW 72
#define VROWW 40
#define FA_STAGE_WORDS (2 * 64 * KROWW + 2 * 128 * VROWW)   // 19456
#define FA_SMEM_BYTES (2 * FA_STAGE_WORDS * 4)              // 155648

__global__ __launch_bounds__(256, 1) void fa_tc_kernel(
    const float* __restrict__ Q,
    const uint32_t* __restrict__ KhiG, const uint32_t* __restrict__ KloG,
    const uint32_t* __restrict__ VhiG, const uint32_t* __restrict__ VloG,
    float* __restrict__ Ar)
{
    extern __shared__ uint32_t su[];
    const uint32_t smem_base = smem_u32(su);

    const int qb = (int)gridDim.x - 1 - (int)blockIdx.x;
    const int h  = blockIdx.y;
    const int b  = blockIdx.z;
    const int t  = threadIdx.x;
    const int w  = t >> 5;
    const int lane = t & 31;
    const int g  = lane >> 2;
    const int t4 = lane & 3;
    const int q0 = qb * 128;

    const size_t bh_off = (size_t)b * Sseq * Dmod + (size_t)h * DKk;
    const size_t bhS = (size_t)(b * Hh + h) * Sseq;
    const size_t bhD = (size_t)(b * Hh + h) * DKk;

    // Preload Q fragments (pre-scaled), split hi/lo
    const float qscale = 0.088388347648318447f * 1.4426950408889634f;
    uint32_t qhi[8][4], qlo[8][4];
    {
        const float* Qw = Q + bh_off + (size_t)(q0 + w * 16) * Dmod;
        #pragma unroll
        for (int ks = 0; ks < 8; ks++) {
            const int d0 = ks * 16 + 2 * t4;
            float2 x0 = *(const float2*)(Qw + (size_t)g * Dmod + d0);
            float2 x1 = *(const float2*)(Qw + (size_t)(g + 8) * Dmod + d0);
            float2 x2 = *(const float2*)(Qw + (size_t)g * Dmod + d0 + 8);
            float2 x3 = *(const float2*)(Qw + (size_t)(g + 8) * Dmod + d0 + 8);
            split2(x0.x * qscale, x0.y * qscale, qhi[ks][0], qlo[ks][0]);
            split2(x1.x * qscale, x1.y * qscale, qhi[ks][1], qlo[ks][1]);
            split2(x2.x * qscale, x2.y * qscale, qhi[ks][2], qlo[ks][2]);
            split2(x3.x * qscale, x3.y * qscale, qhi[ks][3], qlo[ks][3]);
        }
    }

    auto load_tile = [&](int stage, int kt) {
        const int kv0 = kt * 64;
        const uint32_t sb = smem_base + (uint32_t)stage * FA_STAGE_WORDS * 4;
        const uint32_t kh = sb;
        const uint32_t kl = sb + 64 * KROWW * 4;
        const uint32_t vh = sb + 2 * 64 * KROWW * 4;
        const uint32_t vl = vh + 128 * VROWW * 4;
        #pragma unroll
        for (int i = 0; i < 4; i++) {
            int u = t + i * 256;               // 1024 chunks per plane
            int row = u >> 4, w4 = (u & 15) * 4;
            size_t src = (bhS + kv0 + row) * 64 + w4;
            uint32_t doff = (uint32_t)(row * KROWW + w4) * 4;
            CP_ASYNC16(kh + doff, KhiG + src);
            CP_ASYNC16(kl + doff, KloG + src);
        }
        #pragma unroll
        for (int i = 0; i < 4; i++) {
            int u = t + i * 256;
            int row = u >> 3, w4 = (u & 7) * 4;
            size_t src = (bhD + row) * 1024 + (kv0 >> 1) + w4;
            uint32_t doff = (uint32_t)(row * VROWW + w4) * 4;
            CP_ASYNC16(vh + doff, VhiG + src);
            CP_ASYNC16(vl + doff, VloG + src);
        }
    };

    float oacc[16][4];
    #pragma unroll
    for (int nf = 0; nf < 16; nf++)
        #pragma unroll
        for (int r = 0; r < 4; r++) oacc[nf][r] = 0.f;

    float m0 = -1e30f, m1 = -1e30f, l0 = 0.f, l1 = 0.f;
    const int row0 = q0 + w * 16 + g;
    const int row1 = row0 + 8;

    const int ntiles = 2 * qb + 2;
    load_tile(0, 0);
    CP_COMMIT();

    for (int kt = 0; kt < ntiles; kt++) {
        const int st = kt & 1;
        const int kv0 = kt * 64;
        if (kt + 1 < ntiles) {
            load_tile(st ^ 1, kt + 1);
            CP_COMMIT();
            CP_WAIT(1);
        } else {
            CP_WAIT(0);
        }
        __syncthreads();

        const uint32_t* Khi = su + (size_t)st * FA_STAGE_WORDS;
        const uint32_t* Klo = Khi + 64 * KROWW;
        const uint32_t* Vhi = Khi + 2 * 64 * KROWW;
        const uint32_t* Vlo = Vhi + 128 * VROWW;

        // ---- QK^T ----
        float acc[8][4];
        #pragma unroll
        for (int nf = 0; nf < 8; nf++)
            #pragma unroll
            for (int r = 0; r < 4; r++) acc[nf][r] = 0.f;

        #pragma unroll
        for (int ks = 0; ks < 8; ks++) {
            #pragma unroll
            for (int nf = 0; nf < 8; nf++) {
                const int r = (nf * 8 + g) * KROWW + 8 * ks + 2 * t4;
                uint2 bh = *(const uint2*)&Khi[r];
                uint2 bl = *(const uint2*)&Klo[r];
                mma_bf16(acc[nf], qhi[ks], bh.x, bh.y);
                mma_bf16(acc[nf], qhi[ks], bl.x, bl.y);
                mma_bf16(acc[nf], qlo[ks], bh.x, bh.y);
            }
        }

        // ---- causal mask ----
        if (kv0 + 63 > q0) {
            #pragma unroll
            for (int nf = 0; nf < 8; nf++) {
                const int c = kv0 + nf * 8 + 2 * t4;
                if (c     > row0) acc[nf][0] = -1e30f;
                if (c + 1 > row0) acc[nf][1] = -1e30f;
                if (c     > row1) acc[nf][2] = -1e30f;
                if (c + 1 > row1) acc[nf][3] = -1e30f;
            }
        }

        // ---- online softmax (base-2 domain) ----
        float mx0 = -1e30f, mx1 = -1e30f;
        #pragma unroll
        for (int nf = 0; nf < 8; nf++) {
            mx0 = fmaxf(mx0, fmaxf(acc[nf][0], acc[nf][1]));
            mx1 = fmaxf(mx1, fmaxf(acc[nf][2], acc[nf][3]));
        }
        mx0 = fmaxf(mx0, __shfl_xor_sync(0xFFFFFFFFu, mx0, 1));
        mx0 = fmaxf(mx0, __shfl_xor_sync(0xFFFFFFFFu, mx0, 2));
        mx1 = fmaxf(mx1, __shfl_xor_sync(0xFFFFFFFFu, mx1, 1));
        mx1 = fmaxf(mx1, __shfl_xor_sync(0xFFFFFFFFu, mx1, 2));

        const float mn0 = fmaxf(m0, mx0);
        const float mn1 = fmaxf(m1, mx1);
        const float cr0 = ex2(m0 - mn0);
        const float cr1 = ex2(m1 - mn1);

        float ps0 = 0.f, ps1 = 0.f;
        #pragma unroll
        for (int nf = 0; nf < 8; nf++) {
            acc[nf][0] = ex2(acc[nf][0] - mn0);
            acc[nf][1] = ex2(acc[nf][1] - mn0);
            acc[nf][2] = ex2(acc[nf][2] - mn1);
            acc[nf][3] = ex2(acc[nf][3] - mn1);
            ps0 += acc[nf][0] + acc[nf][1];
            ps1 += acc[nf][2] + acc[nf][3];
        }
        ps0 += __shfl_xor_sync(0xFFFFFFFFu, ps0, 1);
        ps0 += __shfl_xor_sync(0xFFFFFFFFu, ps0, 2);
        ps1 += __shfl_xor_sync(0xFFFFFFFFu, ps1, 1);
        ps1 += __shfl_xor_sync(0xFFFFFFFFu, ps1, 2);

        l0 = l0 * cr0 + ps0;
        l1 = l1 * cr1 + ps1;
        m0 = mn0;
        m1 = mn1;

        #pragma unroll
        for (int nf = 0; nf < 16; nf++) {
            oacc[nf][0] *= cr0;
            oacc[nf][1] *= cr0;
            oacc[nf][2] *= cr1;
            oacc[nf][3] *= cr1;
        }

        // ---- P @ V ----
        #pragma unroll
        for (int ks2 = 0; ks2 < 4; ks2++) {
            uint32_t ahi[4], alo[4];
            split2(acc[2 * ks2][0],     acc[2 * ks2][1],     ahi[0], alo[0]);
            split2(acc[2 * ks2][2],     acc[2 * ks2][3],     ahi[1], alo[1]);
            split2(acc[2 * ks2 + 1][0], acc[2 * ks2 + 1][1], ahi[2], alo[2]);
            split2(acc[2 * ks2 + 1][2], acc[2 * ks2 + 1][3], ahi[3], alo[3]);
            #pragma unroll
            for (int nf = 0; nf < 16; nf++) {
                const int r = (nf * 8 + g) * VROWW + 8 * ks2 + 2 * t4;
                uint2 bh = *(const uint2*)&Vhi[r];
                uint2 bl = *(const uint2*)&Vlo[r];
                mma_bf16(oacc[nf], ahi, bh.x, bh.y);
                mma_bf16(oacc[nf], ahi, bl.x, bl.y);
                mma_bf16(oacc[nf], alo, bh.x, bh.y);
            }
        }
        __syncthreads();
    }

    // ---- epilogue: normalize, round to tf32, k-permute, store into Ar ----
    const float inv0 = 1.0f / l0;
    const float inv1 = 1.0f / l1;
    const int p0 = (((2 * t4) & 3) << 1) | (((2 * t4) >> 2) & 1);
    const int p1 = (((2 * t4 + 1) & 3) << 1) | (((2 * t4 + 1) >> 2) & 1);
    float* Ow = Ar + bh_off + (size_t)(q0 + w * 16) * Dmod;
    #pragma unroll
    for (int nf = 0; nf < 16; nf++) {
        const int cb = nf * 8;
        Ow[(size_t)g * Dmod + cb + p0] =
            __uint_as_float(f2tf32(oacc[nf][0] * inv0));
        Ow[(size_t)g * Dmod + cb + p1] =
            __uint_as_float(f2tf32(oacc[nf][1] * inv0));
        Ow[(size_t)(g + 8) * Dmod + cb + p0] =
            __uint_as_float(f2tf32(oacc[nf][2] * inv1));
        Ow[(size_t)(g + 8) * Dmod + cb + p1] =
            __uint_as_float(f2tf32(oacc[nf][3] * inv1));
    }
}

// ---------------------------------------------------------------------------
// kernel_launch
// ---------------------------------------------------------------------------
extern "C" void kernel_launch(void* const* d_in, const int* in_sizes, int n_in,
                              void* d_out, int out_size)
{
    const float* queries = (const float*)d_in[0];
    const float* keys    = (const float*)d_in[1];
    const float* values  = (const float*)d_in[2];
    const float* Wq      = (const float*)d_in[3];
    const float* bq      = (const float*)d_in[4];
    const float* Wlk     = (const float*)d_in[5];
    const float* blk     = (const float*)d_in[6];
    const float* Wlv     = (const float*)d_in[7];
    const float* blv     = (const float*)d_in[8];
    const float* Wkr     = (const float*)d_in[9];
    const float* bkr     = (const float*)d_in[10];
    const float* Wvr     = (const float*)d_in[11];
    const float* bvr     = (const float*)d_in[12];
    const float* Wo      = (const float*)d_in[13];
    const float* bo      = (const float*)d_in[14];
    float* out = (float*)d_out;

    float *Q, *Ar, *WqT, *WkT, *WvT, *WoT, *bk, *bv;
    uint32_t *Khi, *Klo, *Vhi, *Vlo;
    cudaGetSymbolAddress((void**)&Q,   g_Q);
    cudaGetSymbolAddress((void**)&Ar,  g_Ar);
    cudaGetSymbolAddress((void**)&Khi, g_Khi);
    cudaGetSymbolAddress((void**)&Klo, g_Klo);
    cudaGetSymbolAddress((void**)&Vhi, g_Vhi);
    cudaGetSymbolAddress((void**)&Vlo, g_Vlo);
    cudaGetSymbolAddress((void**)&WqT, g_WqT);
    cudaGetSymbolAddress((void**)&WkT, g_WkT);
    cudaGetSymbolAddress((void**)&WvT, g_WvT);
    cudaGetSymbolAddress((void**)&WoT, g_WoT);
    cudaGetSymbolAddress((void**)&bk,  g_bk);
    cudaGetSymbolAddress((void**)&bv,  g_bv);

    cudaFuncSetAttribute(gemm_tc_kernel<0>,
                         cudaFuncAttributeMaxDynamicSharedMemorySize, G_SMEM_BYTES);
    cudaFuncSetAttribute(gemm_tc_kernel<1>,
                         cudaFuncAttributeMaxDynamicSharedMemorySize, G_SMEM_BYTES);
    cudaFuncSetAttribute(gemm_tc_kernel<2>,
                         cudaFuncAttributeMaxDynamicSharedMemorySize, G_SMEM_BYTES);
    cudaFuncSetAttribute(fa_tc_kernel,
                         cudaFuncAttributeMaxDynamicSharedMemorySize, FA_SMEM_BYTES);
    cudaFuncSetAttribute(foldT_kernel,
                         cudaFuncAttributeMaxDynamicSharedMemorySize, FT_SMEM_BYTES);

    const dim3 tgrid(Dmod / 32, Dmod / 32);
    const dim3 ggrid(Dmod / 128, Mrows / 128);
    const dim3 fgrid(16, 16);
    const int rblocks = (int)(((size_t)Mrows * Dmod / 8) / 256);

    // Weight preparation
    foldT_kernel<<<fgrid, 256, FT_SMEM_BYTES>>>(Wlk, Wkr, WkT);
    fold_b_kernel<<<Hh, 128>>>(blk, Wkr, bkr, bk);
    foldT_kernel<<<fgrid, 256, FT_SMEM_BYTES>>>(Wlv, Wvr, WvT);
    fold_b_kernel<<<Hh, 128>>>(blv, Wvr, bvr, bv);
    transpose_kernel<<<tgrid, 256>>>(Wq, WqT);
    transpose_kernel<<<tgrid, 256>>>(Wo, WoT);

    // Q projection
    round_perm_kernel<<<rblocks, 256>>>(queries, Ar);
    gemm_tc_kernel<0><<<ggrid, 256, G_SMEM_BYTES>>>(Ar, WqT, bq, Q, nullptr, nullptr);

    // K projection -> split bf16 planes
    round_perm_kernel<<<rblocks, 256>>>(keys, Ar);
    gemm_tc_kernel<1><<<ggrid, 256, G_SMEM_BYTES>>>(Ar, WkT, bk, nullptr, Khi, Klo);

    // V projection -> split bf16 planes, transposed
    round_perm_kernel<<<rblocks, 256>>>(values, Ar);
    gemm_tc_kernel<2><<<ggrid, 256, G_SMEM_BYTES>>>(Ar, WvT, bv, nullptr, Vhi, Vlo);

    // Fused causal attention (writes rounded+permuted output into Ar)
    fa_tc_kernel<<<dim3(Sseq / 128, Hh, Bsz), 256, FA_SMEM_BYTES>>>(
        Q, Khi, Klo, Vhi, Vlo, Ar);

    // Output projection
    gemm_tc_kernel<0><<<ggrid, 256, G_SMEM_BYTES>>>(Ar, WoT, bo, out, nullptr, nullptr);
}